// round 10
// baseline (speedup 1.0000x reference)
#include <cuda_runtime.h>
#include <cuda_bf16.h>
#include <cstdint>

// ---------------------------------------------------------------------------
// Problem constants
// ---------------------------------------------------------------------------
#define BATCH 2
#define SEQ   2048
#define EMB   1024
#define HEADS 16
#define HDIM  64
#define MLPH  4096
#define MTOT  (BATCH * SEQ)   // 4096 rows

// ---------------------------------------------------------------------------
// Scratch (device globals: allocation-free)
// ---------------------------------------------------------------------------
__device__ float g_xn [MTOT * EMB];
__device__ float g_q  [MTOT * EMB];
__device__ float g_k  [MTOT * EMB];
__device__ float g_v  [MTOT * EMB];
__device__ float g_att[MTOT * EMB];
__device__ float g_x2 [MTOT * EMB];
__device__ float g_xn2[MTOT * EMB];
__device__ float g_h  [MTOT * MLPH];

// ---------------------------------------------------------------------------
// Helpers
// ---------------------------------------------------------------------------
__device__ __forceinline__ uint32_t f2tf(float f) {
    uint32_t u;
    asm("cvt.rna.tf32.f32 %0, %1;" : "=r"(u) : "f"(f));
    return u;
}
__device__ __forceinline__ float ex2(float x) {
    float r;
    asm("ex2.approx.f32 %0, %1;" : "=f"(r) : "f"(x));
    return r;
}
__device__ __forceinline__ void mma_tf32(
    float* c, uint32_t a0, uint32_t a1, uint32_t a2, uint32_t a3,
    uint32_t b0, uint32_t b1)
{
    asm volatile(
        "mma.sync.aligned.m16n8k8.row.col.f32.tf32.tf32.f32 "
        "{%0,%1,%2,%3}, {%4,%5,%6,%7}, {%8,%9}, {%0,%1,%2,%3};"
        : "+f"(c[0]), "+f"(c[1]), "+f"(c[2]), "+f"(c[3])
        : "r"(a0), "r"(a1), "r"(a2), "r"(a3), "r"(b0), "r"(b1));
}

// ---------------------------------------------------------------------------
// LayerNorm: one block per row of 1024, 256 threads, float4
// ---------------------------------------------------------------------------
__global__ __launch_bounds__(256) void ln_kernel(
    const float* __restrict__ x, const float* __restrict__ g,
    const float* __restrict__ b, float* __restrict__ y)
{
    int row = blockIdx.x;
    int tid = threadIdx.x;
    const float4 v = ((const float4*)(x + (size_t)row * EMB))[tid];

    float s  = v.x + v.y + v.z + v.w;
    float ss = v.x * v.x + v.y * v.y + v.z * v.z + v.w * v.w;
    #pragma unroll
    for (int o = 16; o; o >>= 1) {
        s  += __shfl_xor_sync(0xffffffffu, s,  o);
        ss += __shfl_xor_sync(0xffffffffu, ss, o);
    }
    __shared__ float rs[8], rss[8];
    int w = tid >> 5, lane = tid & 31;
    if (lane == 0) { rs[w] = s; rss[w] = ss; }
    __syncthreads();
    s = 0.f; ss = 0.f;
    #pragma unroll
    for (int i = 0; i < 8; i++) { s += rs[i]; ss += rss[i]; }

    const float mean = s * (1.0f / EMB);
    const float var  = ss * (1.0f / EMB) - mean * mean;
    const float rstd = rsqrtf(var + 1e-5f);

    const float4 gv = ((const float4*)g)[tid];
    const float4 bv = ((const float4*)b)[tid];
    float4 o;
    o.x = (v.x - mean) * rstd * gv.x + bv.x;
    o.y = (v.y - mean) * rstd * gv.y + bv.y;
    o.z = (v.z - mean) * rstd * gv.z + bv.z;
    o.w = (v.w - mean) * rstd * gv.w + bv.w;
    ((float4*)(y + (size_t)row * EMB))[tid] = o;
}

// ---------------------------------------------------------------------------
// TF32 tensor-core GEMM, 2-stage double-buffered smem.
// C = A[MxK] @ B[KxN] + bias (+ residual / relu)
// CTA 128x256, BK=16, 256 threads (8 warps), warp tile 64x64 (m16n8k8 mma).
// One __syncthreads per K-tile; global prefetch + commit of tile k+1
// overlaps mma of tile k.
// EPI: 0 = bias, 1 = bias+relu, 2 = bias+residual
// ---------------------------------------------------------------------------
#define BM 128
#define BN 256
#define BK 16
#define AST 136
#define BST 264
#define STG_A (BK * AST)
#define STG_B (BK * BST)
#define GEMM_SMEM ((2 * STG_A + 2 * STG_B) * 4)   // 51200 B

template<int EPI>
__device__ __forceinline__ void tgemm_body(
    const float* __restrict__ A, const float* __restrict__ B,
    const float* __restrict__ bias, const float* __restrict__ R,
    float* __restrict__ C, int M, int N, int K, int m0, int n0,
    uint32_t* Asm, uint32_t* Bsm)
{
    const int tid  = threadIdx.x;
    const int warp = tid >> 5;
    const int lane = tid & 31;
    const int gr   = lane >> 2;    // 0..7
    const int gc   = lane & 3;     // 0..3
    const int wm   = (warp & 1) * 64;
    const int wn   = (warp >> 1) * 64;

    const int ar0 = tid >> 2,           ac0 = (tid & 3) * 4;
    const int ar1 = (tid + 256) >> 2,   ac1 = ((tid + 256) & 3) * 4;
    const int br[4] = { tid >> 6, (tid + 256) >> 6, (tid + 512) >> 6, (tid + 768) >> 6 };
    const int bc    = (tid & 63) * 4;

    const float* Ab = A + (size_t)m0 * K;
    const float* Bb = B + n0;

    const int nkt = K / BK;

    // load tile 0
    float4 pa0 = *(const float4*)(Ab + (size_t)ar0 * K + ac0);
    float4 pa1 = *(const float4*)(Ab + (size_t)ar1 * K + ac1);
    float4 pb[4];
    #pragma unroll
    for (int t = 0; t < 4; t++)
        pb[t] = *(const float4*)(Bb + (size_t)br[t] * N + bc);

    // commit tile 0 -> stage 0
    {
        uint32_t* As = Asm;
        uint32_t* Bs = Bsm;
        As[(ac0 + 0) * AST + ar0] = f2tf(pa0.x);
        As[(ac0 + 1) * AST + ar0] = f2tf(pa0.y);
        As[(ac0 + 2) * AST + ar0] = f2tf(pa0.z);
        As[(ac0 + 3) * AST + ar0] = f2tf(pa0.w);
        As[(ac1 + 0) * AST + ar1] = f2tf(pa1.x);
        As[(ac1 + 1) * AST + ar1] = f2tf(pa1.y);
        As[(ac1 + 2) * AST + ar1] = f2tf(pa1.z);
        As[(ac1 + 3) * AST + ar1] = f2tf(pa1.w);
        #pragma unroll
        for (int t = 0; t < 4; t++) {
            uint4 u;
            u.x = f2tf(pb[t].x); u.y = f2tf(pb[t].y);
            u.z = f2tf(pb[t].z); u.w = f2tf(pb[t].w);
            *(uint4*)&Bs[br[t] * BST + bc] = u;
        }
    }
    __syncthreads();

    // prefetch tile 1
    if (nkt > 1) {
        pa0 = *(const float4*)(Ab + (size_t)ar0 * K + BK + ac0);
        pa1 = *(const float4*)(Ab + (size_t)ar1 * K + BK + ac1);
        #pragma unroll
        for (int t = 0; t < 4; t++)
            pb[t] = *(const float4*)(Bb + (size_t)(BK + br[t]) * N + bc);
    }

    float acc[4][8][4];
    #pragma unroll
    for (int mt = 0; mt < 4; mt++)
        #pragma unroll
        for (int nt = 0; nt < 8; nt++)
            #pragma unroll
            for (int r = 0; r < 4; r++) acc[mt][nt][r] = 0.f;

    for (int kt = 0; kt < nkt; kt++) {
        const int cur = kt & 1;
        uint32_t* As = Asm + cur * STG_A;
        uint32_t* Bs = Bsm + cur * STG_B;

        // mma over current stage
        #pragma unroll
        for (int ks = 0; ks < BK; ks += 8) {
            uint32_t af[4][4];
            #pragma unroll
            for (int mt = 0; mt < 4; mt++) {
                const int m = wm + mt * 16 + gr;
                const int ka = ks + gc;
                af[mt][0] = As[ka * AST + m];
                af[mt][1] = As[ka * AST + m + 8];
                af[mt][2] = As[(ka + 4) * AST + m];
                af[mt][3] = As[(ka + 4) * AST + m + 8];
            }
            #pragma unroll
            for (int nt = 0; nt < 8; nt++) {
                const int n = wn + nt * 8 + gr;
                const uint32_t b0 = Bs[(ks + gc) * BST + n];
                const uint32_t b1 = Bs[(ks + gc + 4) * BST + n];
                #pragma unroll
                for (int mt = 0; mt < 4; mt++)
                    mma_tf32(acc[mt][nt], af[mt][0], af[mt][1], af[mt][2], af[mt][3],
                             b0, b1);
            }
        }

        if (kt + 1 < nkt) {
            // commit prefetched tile -> other stage (safe: last read of that
            // stage was at kt-1, guarded by the syncthreads below at kt-1)
            uint32_t* An = Asm + (cur ^ 1) * STG_A;
            uint32_t* Bn = Bsm + (cur ^ 1) * STG_B;
            An[(ac0 + 0) * AST + ar0] = f2tf(pa0.x);
            An[(ac0 + 1) * AST + ar0] = f2tf(pa0.y);
            An[(ac0 + 2) * AST + ar0] = f2tf(pa0.z);
            An[(ac0 + 3) * AST + ar0] = f2tf(pa0.w);
            An[(ac1 + 0) * AST + ar1] = f2tf(pa1.x);
            An[(ac1 + 1) * AST + ar1] = f2tf(pa1.y);
            An[(ac1 + 2) * AST + ar1] = f2tf(pa1.z);
            An[(ac1 + 3) * AST + ar1] = f2tf(pa1.w);
            #pragma unroll
            for (int t = 0; t < 4; t++) {
                uint4 u;
                u.x = f2tf(pb[t].x); u.y = f2tf(pb[t].y);
                u.z = f2tf(pb[t].z); u.w = f2tf(pb[t].w);
                *(uint4*)&Bn[br[t] * BST + bc] = u;
            }
            __syncthreads();

            if (kt + 2 < nkt) {  // prefetch tile kt+2 (hidden under next mma)
                const int k0 = (kt + 2) * BK;
                pa0 = *(const float4*)(Ab + (size_t)ar0 * K + k0 + ac0);
                pa1 = *(const float4*)(Ab + (size_t)ar1 * K + k0 + ac1);
                #pragma unroll
                for (int t = 0; t < 4; t++)
                    pb[t] = *(const float4*)(Bb + (size_t)(k0 + br[t]) * N + bc);
            }
        }
    }

    float2 bv[8];
    #pragma unroll
    for (int nt = 0; nt < 8; nt++)
        bv[nt] = *(const float2*)(bias + n0 + wn + nt * 8 + gc * 2);

    #pragma unroll
    for (int mt = 0; mt < 4; mt++) {
        const int gm = m0 + wm + mt * 16 + gr;
        #pragma unroll
        for (int nt = 0; nt < 8; nt++) {
            const int gn = n0 + wn + nt * 8 + gc * 2;
            float2 o0, o1;
            o0.x = acc[mt][nt][0] + bv[nt].x;
            o0.y = acc[mt][nt][1] + bv[nt].y;
            o1.x = acc[mt][nt][2] + bv[nt].x;
            o1.y = acc[mt][nt][3] + bv[nt].y;
            if (EPI == 1) {
                o0.x = fmaxf(o0.x, 0.f); o0.y = fmaxf(o0.y, 0.f);
                o1.x = fmaxf(o1.x, 0.f); o1.y = fmaxf(o1.y, 0.f);
            }
            if (EPI == 2) {
                const float2 r0 = *(const float2*)(R + (size_t)gm * N + gn);
                const float2 r1 = *(const float2*)(R + (size_t)(gm + 8) * N + gn);
                o0.x += r0.x; o0.y += r0.y;
                o1.x += r1.x; o1.y += r1.y;
            }
            *(float2*)(C + (size_t)gm * N + gn)       = o0;
            *(float2*)(C + (size_t)(gm + 8) * N + gn) = o1;
        }
    }
}

template<int EPI>
__global__ __launch_bounds__(256, 1) void tgemm_kernel(
    const float* __restrict__ A, const float* __restrict__ B,
    const float* __restrict__ bias, const float* __restrict__ R,
    float* __restrict__ C, int M, int N, int K)
{
    extern __shared__ uint32_t smg[];
    tgemm_body<EPI>(A, B, bias, R, C, M, N, K,
                    blockIdx.y * BM, blockIdx.x * BN, smg, smg + 2 * STG_A);
}

__global__ __launch_bounds__(256, 1) void qkv_kernel(
    const float* __restrict__ A,
    const float* __restrict__ B0, const float* __restrict__ B1, const float* __restrict__ B2,
    const float* __restrict__ b0, const float* __restrict__ b1, const float* __restrict__ b2,
    float* __restrict__ C0, float* __restrict__ C1, float* __restrict__ C2)
{
    extern __shared__ uint32_t smg[];
    const float* B = (blockIdx.z == 0) ? B0 : (blockIdx.z == 1) ? B1 : B2;
    const float* bb = (blockIdx.z == 0) ? b0 : (blockIdx.z == 1) ? b1 : b2;
    float* C = (blockIdx.z == 0) ? C0 : (blockIdx.z == 1) ? C1 : C2;
    tgemm_body<0>(A, B, bb, nullptr, C, MTOT, EMB, EMB,
                  blockIdx.y * BM, blockIdx.x * BN, smg, smg + 2 * STG_A);
}

// ---------------------------------------------------------------------------
// Flash-attention v3: tf32 tensor cores + log2-domain online softmax.
// (unchanged from round 9 — proven at ~310 us)
// ---------------------------------------------------------------------------
#define AQT 128
#define AKT 64
#define QP 68    // 68 mod 32 = 4
#define KP 72    // 72 mod 32 = 8
#define ATT_SMEM ((128*QP + 64*KP + 64*KP + 128*QP) * 4)   // 106496 B
#define QSCALE 0.18033688011112042f   // 0.125 * log2(e)

__global__ __launch_bounds__(256, 1) void attn3_kernel(
    const float* __restrict__ Q, const float* __restrict__ Km,
    const float* __restrict__ Vm, float* __restrict__ O)
{
    extern __shared__ uint32_t smu[];
    uint32_t* sQ = smu;
    uint32_t* sK = sQ + 128 * QP;
    uint32_t* sV = sK + 64 * KP;
    uint32_t* sP = sV + 64 * KP;

    const int bh = blockIdx.y;
    const int b  = bh / HEADS;
    const int h  = bh % HEADS;
    const int q0 = blockIdx.x * AQT;
    const int tid  = threadIdx.x;
    const int warp = tid >> 5;
    const int lane = tid & 31;
    const int gr   = lane >> 2;
    const int gc   = lane & 3;
    const int wq0  = warp * 16;
    uint32_t* sPw = sP + warp * 16 * QP;

    const size_t base = ((size_t)b * SEQ) * EMB + (size_t)h * HDIM;
    const float* Qb = Q  + base;
    const float* Kb = Km + base;
    const float* Vb = Vm + base;

    #pragma unroll
    for (int t = 0; t < 8; t++) {
        int idx = tid + t * 256;
        int qr = idx >> 4, c4 = (idx & 15) * 4;
        float4 v = *(const float4*)(Qb + (size_t)(q0 + qr) * EMB + c4);
        sQ[qr * QP + c4 + 0] = f2tf(v.x * QSCALE);
        sQ[qr * QP + c4 + 1] = f2tf(v.y * QSCALE);
        sQ[qr * QP + c4 + 2] = f2tf(v.z * QSCALE);
        sQ[qr * QP + c4 + 3] = f2tf(v.w * QSCALE);
    }

    float m0 = -1e30f, m1 = -1e30f, l0 = 0.f, l1 = 0.f;
    float oacc[8][4];
    #pragma unroll
    for (int nt = 0; nt < 8; nt++)
        #pragma unroll
        for (int r = 0; r < 4; r++) oacc[nt][r] = 0.f;

    const int kr0 = tid >> 4;
    const int kc4 = (tid & 15) * 4;
    float4 pk[4], pv[4];
    #pragma unroll
    for (int t = 0; t < 4; t++) {
        size_t goff = (size_t)(kr0 + t * 16) * EMB + kc4;
        pk[t] = *(const float4*)(Kb + goff);
        pv[t] = *(const float4*)(Vb + goff);
    }

    for (int kt = 0; kt < SEQ / AKT; kt++) {
        #pragma unroll
        for (int t = 0; t < 4; t++) {
            int kr = kr0 + t * 16;
            sK[(kc4 + 0) * KP + kr] = f2tf(pk[t].x);
            sK[(kc4 + 1) * KP + kr] = f2tf(pk[t].y);
            sK[(kc4 + 2) * KP + kr] = f2tf(pk[t].z);
            sK[(kc4 + 3) * KP + kr] = f2tf(pk[t].w);
            uint4 u;
            u.x = f2tf(pv[t].x); u.y = f2tf(pv[t].y);
            u.z = f2tf(pv[t].z); u.w = f2tf(pv[t].w);
            *(uint4*)&sV[kr * KP + kc4] = u;
        }
        __syncthreads();

        if (kt + 1 < SEQ / AKT) {
            const size_t tb = (size_t)(kt + 1) * AKT * EMB;
            #pragma unroll
            for (int t = 0; t < 4; t++) {
                size_t goff = tb + (size_t)(kr0 + t * 16) * EMB + kc4;
                pk[t] = *(const float4*)(Kb + goff);
                pv[t] = *(const float4*)(Vb + goff);
            }
        }

        float sacc[8][4];
        #pragma unroll
        for (int nt = 0; nt < 8; nt++)
            #pragma unroll
            for (int r = 0; r < 4; r++) sacc[nt][r] = 0.f;

        #pragma unroll
        for (int ks = 0; ks < 8; ks++) {
            const int ka = ks * 8 + gc;
            const uint32_t a0 = sQ[(wq0 + gr) * QP + ka];
            const uint32_t a1 = sQ[(wq0 + gr + 8) * QP + ka];
            const uint32_t a2 = sQ[(wq0 + gr) * QP + ka + 4];
            const uint32_t a3 = sQ[(wq0 + gr + 8) * QP + ka + 4];
            #pragma unroll
            for (int nt = 0; nt < 8; nt++) {
                const uint32_t b0 = sK[ka * KP + nt * 8 + gr];
                const uint32_t b1 = sK[(ka + 4) * KP + nt * 8 + gr];
                mma_tf32(sacc[nt], a0, a1, a2, a3, b0, b1);
            }
        }

        float t0 = -1e30f, t1 = -1e30f;
        #pragma unroll
        for (int nt = 0; nt < 8; nt++) {
            t0 = fmaxf(t0, fmaxf(sacc[nt][0], sacc[nt][1]));
            t1 = fmaxf(t1, fmaxf(sacc[nt][2], sacc[nt][3]));
        }
        t0 = fmaxf(t0, __shfl_xor_sync(0xffffffffu, t0, 1));
        t0 = fmaxf(t0, __shfl_xor_sync(0xffffffffu, t0, 2));
        t1 = fmaxf(t1, __shfl_xor_sync(0xffffffffu, t1, 1));
        t1 = fmaxf(t1, __shfl_xor_sync(0xffffffffu, t1, 2));
        const float nm0 = fmaxf(m0, t0);
        const float nm1 = fmaxf(m1, t1);
        const float c0 = ex2(m0 - nm0);
        const float c1 = ex2(m1 - nm1);
        float ps0 = 0.f, ps1 = 0.f;
        #pragma unroll
        for (int nt = 0; nt < 8; nt++) {
            const float p00 = ex2(sacc[nt][0] - nm0);
            const float p01 = ex2(sacc[nt][1] - nm0);
            const float p10 = ex2(sacc[nt][2] - nm1);
            const float p11 = ex2(sacc[nt][3] - nm1);
            ps0 += p00 + p01;
            ps1 += p10 + p11;
            sPw[gr * QP + nt * 8 + gc * 2]           = f2tf(p00);
            sPw[gr * QP + nt * 8 + gc * 2 + 1]       = f2tf(p01);
            sPw[(gr + 8) * QP + nt * 8 + gc * 2]     = f2tf(p10);
            sPw[(gr + 8) * QP + nt * 8 + gc * 2 + 1] = f2tf(p11);
        }
        ps0 += __shfl_xor_sync(0xffffffffu, ps0, 1);
        ps0 += __shfl_xor_sync(0xffffffffu, ps0, 2);
        ps1 += __shfl_xor_sync(0xffffffffu, ps1, 1);
        ps1 += __shfl_xor_sync(0xffffffffu, ps1, 2);
        l0 = l0 * c0 + ps0;
        l1 = l1 * c1 + ps1;
        m0 = nm0; m1 = nm1;
        #pragma unroll
        for (int nt = 0; nt < 8; nt++) {
            oacc[nt][0] *= c0; oacc[nt][1] *= c0;
            oacc[nt][2] *= c1; oacc[nt][3] *= c1;
        }
        __syncwarp();

        #pragma unroll
        for (int ks = 0; ks < 8; ks++) {
            const int kk = ks * 8 + gc;
            const uint32_t a0 = sPw[gr * QP + kk];
            const uint32_t a1 = sPw[(gr + 8) * QP + kk];
            const uint32_t a2 = sPw[gr * QP + kk + 4];
            const uint32_t a3 = sPw[(gr + 8) * QP + kk + 4];
            #pragma unroll
            for (int nt = 0; nt < 8; nt++) {
                const uint32_t b0 = sV[kk * KP + nt * 8 + gr];
                const uint32_t b1 = sV[(kk + 4) * KP + nt * 8 + gr];
                mma_tf32(oacc[nt], a0, a1, a2, a3, b0, b1);
            }
        }
        __syncthreads();
    }

    const float inv0 = 1.0f / l0;
    const float inv1 = 1.0f / l1;
    float* O0 = O + base + (size_t)(q0 + wq0 + gr) * EMB;
    float* O1 = O + base + (size_t)(q0 + wq0 + gr + 8) * EMB;
    #pragma unroll
    for (int nt = 0; nt < 8; nt++) {
        const int cn = nt * 8 + gc * 2;
        float2 x0, x1;
        x0.x = oacc[nt][0] * inv0; x0.y = oacc[nt][1] * inv0;
        x1.x = oacc[nt][2] * inv1; x1.y = oacc[nt][3] * inv1;
        *(float2*)(O0 + cn) = x0;
        *(float2*)(O1 + cn) = x1;
    }
}

// ---------------------------------------------------------------------------
// Launch
// ---------------------------------------------------------------------------
extern "C" void kernel_launch(void* const* d_in, const int* in_sizes, int n_in,
                              void* d_out, int out_size)
{
    const float* x    = (const float*)d_in[0];
    const float* ln1g = (const float*)d_in[1];
    const float* ln1b = (const float*)d_in[2];
    const float* ln2g = (const float*)d_in[3];
    const float* ln2b = (const float*)d_in[4];
    const float* Wq   = (const float*)d_in[5];
    const float* bq   = (const float*)d_in[6];
    const float* Wk   = (const float*)d_in[7];
    const float* bk   = (const float*)d_in[8];
    const float* Wv   = (const float*)d_in[9];
    const float* bv   = (const float*)d_in[10];
    const float* Wo   = (const float*)d_in[11];
    const float* bo   = (const float*)d_in[12];
    const float* W1   = (const float*)d_in[13];
    const float* b1   = (const float*)d_in[14];
    const float* W2   = (const float*)d_in[15];
    const float* b2   = (const float*)d_in[16];
    float* out = (float*)d_out;

    float *xn, *q, *k, *v, *att, *x2, *xn2, *hb;
    cudaGetSymbolAddress((void**)&xn,  g_xn);
    cudaGetSymbolAddress((void**)&q,   g_q);
    cudaGetSymbolAddress((void**)&k,   g_k);
    cudaGetSymbolAddress((void**)&v,   g_v);
    cudaGetSymbolAddress((void**)&att, g_att);
    cudaGetSymbolAddress((void**)&x2,  g_x2);
    cudaGetSymbolAddress((void**)&xn2, g_xn2);
    cudaGetSymbolAddress((void**)&hb,  g_h);

    cudaFuncSetAttribute(attn3_kernel,
                         cudaFuncAttributeMaxDynamicSharedMemorySize, ATT_SMEM);
    cudaFuncSetAttribute(tgemm_kernel<1>,
                         cudaFuncAttributeMaxDynamicSharedMemorySize, GEMM_SMEM);
    cudaFuncSetAttribute(tgemm_kernel<2>,
                         cudaFuncAttributeMaxDynamicSharedMemorySize, GEMM_SMEM);
    cudaFuncSetAttribute(qkv_kernel,
                         cudaFuncAttributeMaxDynamicSharedMemorySize, GEMM_SMEM);

    const dim3 blk(256);
    const dim3 gQKV(EMB / BN, MTOT / BM, 3);
    const dim3 gEmb(EMB / BN, MTOT / BM);
    const dim3 gMlp(MLPH / BN, MTOT / BM);
    const dim3 gAtt(SEQ / AQT, BATCH * HEADS);

    // 1. LN1
    ln_kernel<<<MTOT, blk>>>(x, ln1g, ln1b, xn);
    // 2. QKV projections (fused launch, tf32 tensor cores, double-buffered)
    qkv_kernel<<<gQKV, blk, GEMM_SMEM>>>(xn, Wq, Wk, Wv, bq, bk, bv, q, k, v);
    // 3. Attention (tf32 tensor cores)
    attn3_kernel<<<gAtt, blk, ATT_SMEM>>>(q, k, v, att);
    // 4. Output projection + residual
    tgemm_kernel<2><<<gEmb, blk, GEMM_SMEM>>>(att, Wo, bo, x, x2, MTOT, EMB, EMB);
    // 5. LN2
    ln_kernel<<<MTOT, blk>>>(x2, ln2g, ln2b, xn2);
    // 6. MLP up + ReLU
    tgemm_kernel<1><<<gMlp, blk, GEMM_SMEM>>>(xn2, W1, b1, nullptr, hb, MTOT, MLPH, EMB);
    // 7. MLP down + residual -> output
    tgemm_kernel<2><<<gEmb, blk, GEMM_SMEM>>>(hb, W2, b2, x2, out, MTOT, EMB, MLPH);
}

// round 11
// speedup vs baseline: 1.0024x; 1.0024x over previous
#include <cuda_runtime.h>
#include <cuda_bf16.h>
#include <cstdint>

// ---------------------------------------------------------------------------
// Problem constants
// ---------------------------------------------------------------------------
#define BATCH 2
#define SEQ   2048
#define EMB   1024
#define HEADS 16
#define HDIM  64
#define MLPH  4096
#define MTOT  (BATCH * SEQ)   // 4096 rows

// ---------------------------------------------------------------------------
// Scratch (device globals: allocation-free)
// ---------------------------------------------------------------------------
__device__ float g_xn [MTOT * EMB];
__device__ float g_q  [MTOT * EMB];
__device__ float g_k  [MTOT * EMB];
__device__ float g_v  [MTOT * EMB];
__device__ float g_att[MTOT * EMB];
__device__ float g_x2 [MTOT * EMB];
__device__ float g_xn2[MTOT * EMB];
__device__ float g_h  [MTOT * MLPH];

// ---------------------------------------------------------------------------
// Helpers
// ---------------------------------------------------------------------------
__device__ __forceinline__ uint32_t f2tf(float f) {
    uint32_t u;
    asm("cvt.rna.tf32.f32 %0, %1;" : "=r"(u) : "f"(f));
    return u;
}
__device__ __forceinline__ float ex2(float x) {
    float r;
    asm("ex2.approx.f32 %0, %1;" : "=f"(r) : "f"(x));
    return r;
}
__device__ __forceinline__ void mma_tf32(
    float* c, uint32_t a0, uint32_t a1, uint32_t a2, uint32_t a3,
    uint32_t b0, uint32_t b1)
{
    asm volatile(
        "mma.sync.aligned.m16n8k8.row.col.f32.tf32.tf32.f32 "
        "{%0,%1,%2,%3}, {%4,%5,%6,%7}, {%8,%9}, {%0,%1,%2,%3};"
        : "+f"(c[0]), "+f"(c[1]), "+f"(c[2]), "+f"(c[3])
        : "r"(a0), "r"(a1), "r"(a2), "r"(a3), "r"(b0), "r"(b1));
}

// ---------------------------------------------------------------------------
// LayerNorm: one block per row of 1024, 256 threads, float4
// ---------------------------------------------------------------------------
__global__ __launch_bounds__(256) void ln_kernel(
    const float* __restrict__ x, const float* __restrict__ g,
    const float* __restrict__ b, float* __restrict__ y)
{
    int row = blockIdx.x;
    int tid = threadIdx.x;
    const float4 v = ((const float4*)(x + (size_t)row * EMB))[tid];

    float s  = v.x + v.y + v.z + v.w;
    float ss = v.x * v.x + v.y * v.y + v.z * v.z + v.w * v.w;
    #pragma unroll
    for (int o = 16; o; o >>= 1) {
        s  += __shfl_xor_sync(0xffffffffu, s,  o);
        ss += __shfl_xor_sync(0xffffffffu, ss, o);
    }
    __shared__ float rs[8], rss[8];
    int w = tid >> 5, lane = tid & 31;
    if (lane == 0) { rs[w] = s; rss[w] = ss; }
    __syncthreads();
    s = 0.f; ss = 0.f;
    #pragma unroll
    for (int i = 0; i < 8; i++) { s += rs[i]; ss += rss[i]; }

    const float mean = s * (1.0f / EMB);
    const float var  = ss * (1.0f / EMB) - mean * mean;
    const float rstd = rsqrtf(var + 1e-5f);

    const float4 gv = ((const float4*)g)[tid];
    const float4 bv = ((const float4*)b)[tid];
    float4 o;
    o.x = (v.x - mean) * rstd * gv.x + bv.x;
    o.y = (v.y - mean) * rstd * gv.y + bv.y;
    o.z = (v.z - mean) * rstd * gv.z + bv.z;
    o.w = (v.w - mean) * rstd * gv.w + bv.w;
    ((float4*)(y + (size_t)row * EMB))[tid] = o;
}

// ---------------------------------------------------------------------------
// TF32 tensor-core GEMM, 2-stage double-buffered smem, low-register tiles.
// C = A[MxK] @ B[KxN] + bias (+ residual / relu)
// CTA 128x128, BK=16, 256 threads (8 warps), warp tile 64x32 (m16n8k8 mma).
// acc = 64 regs/thread -> fits 128-reg cap -> 2 CTAs/SM.
// EPI: 0 = bias, 1 = bias+relu, 2 = bias+residual
// Requires M%128==0, N%128==0, K%16==0.
// ---------------------------------------------------------------------------
#define BM 128
#define BN 128
#define BK 16
#define AST 136
#define BST 136
#define STG_A (BK * AST)
#define STG_B (BK * BST)
#define GEMM_SMEM ((2 * STG_A + 2 * STG_B) * 4)   // 34816 B

template<int EPI>
__device__ __forceinline__ void tgemm_body(
    const float* __restrict__ A, const float* __restrict__ B,
    const float* __restrict__ bias, const float* __restrict__ R,
    float* __restrict__ C, int M, int N, int K, int m0, int n0,
    uint32_t* Asm, uint32_t* Bsm)
{
    const int tid  = threadIdx.x;
    const int warp = tid >> 5;
    const int lane = tid & 31;
    const int gr   = lane >> 2;    // 0..7
    const int gc   = lane & 3;     // 0..3
    const int wm   = (warp & 1) * 64;
    const int wn   = (warp >> 1) * 32;

    // A loader: 128x16 tile = 512 float4, 2/thread
    const int ar0 = tid >> 2,           ac0 = (tid & 3) * 4;
    const int ar1 = (tid + 256) >> 2,   ac1 = ((tid + 256) & 3) * 4;
    // B loader: 16x128 tile = 512 float4, 2/thread
    const int br0 = tid >> 5,           bc0 = (tid & 31) * 4;
    const int br1 = (tid + 256) >> 5,   bc1 = ((tid + 256) & 31) * 4;

    const float* Ab = A + (size_t)m0 * K;
    const float* Bb = B + n0;

    const int nkt = K / BK;

    // load tile 0
    float4 pa0 = *(const float4*)(Ab + (size_t)ar0 * K + ac0);
    float4 pa1 = *(const float4*)(Ab + (size_t)ar1 * K + ac1);
    float4 pb0 = *(const float4*)(Bb + (size_t)br0 * N + bc0);
    float4 pb1 = *(const float4*)(Bb + (size_t)br1 * N + bc1);

    // commit tile 0 -> stage 0
    {
        uint32_t* As = Asm;
        uint32_t* Bs = Bsm;
        As[(ac0 + 0) * AST + ar0] = f2tf(pa0.x);
        As[(ac0 + 1) * AST + ar0] = f2tf(pa0.y);
        As[(ac0 + 2) * AST + ar0] = f2tf(pa0.z);
        As[(ac0 + 3) * AST + ar0] = f2tf(pa0.w);
        As[(ac1 + 0) * AST + ar1] = f2tf(pa1.x);
        As[(ac1 + 1) * AST + ar1] = f2tf(pa1.y);
        As[(ac1 + 2) * AST + ar1] = f2tf(pa1.z);
        As[(ac1 + 3) * AST + ar1] = f2tf(pa1.w);
        uint4 u0, u1;
        u0.x = f2tf(pb0.x); u0.y = f2tf(pb0.y); u0.z = f2tf(pb0.z); u0.w = f2tf(pb0.w);
        u1.x = f2tf(pb1.x); u1.y = f2tf(pb1.y); u1.z = f2tf(pb1.z); u1.w = f2tf(pb1.w);
        *(uint4*)&Bs[br0 * BST + bc0] = u0;
        *(uint4*)&Bs[br1 * BST + bc1] = u1;
    }
    __syncthreads();

    // prefetch tile 1
    if (nkt > 1) {
        pa0 = *(const float4*)(Ab + (size_t)ar0 * K + BK + ac0);
        pa1 = *(const float4*)(Ab + (size_t)ar1 * K + BK + ac1);
        pb0 = *(const float4*)(Bb + (size_t)(BK + br0) * N + bc0);
        pb1 = *(const float4*)(Bb + (size_t)(BK + br1) * N + bc1);
    }

    float acc[4][4][4];
    #pragma unroll
    for (int mt = 0; mt < 4; mt++)
        #pragma unroll
        for (int nt = 0; nt < 4; nt++)
            #pragma unroll
            for (int r = 0; r < 4; r++) acc[mt][nt][r] = 0.f;

    for (int kt = 0; kt < nkt; kt++) {
        const int cur = kt & 1;
        uint32_t* As = Asm + cur * STG_A;
        uint32_t* Bs = Bsm + cur * STG_B;

        // mma over current stage
        #pragma unroll
        for (int ks = 0; ks < BK; ks += 8) {
            uint32_t af[4][4];
            #pragma unroll
            for (int mt = 0; mt < 4; mt++) {
                const int m = wm + mt * 16 + gr;
                const int ka = ks + gc;
                af[mt][0] = As[ka * AST + m];
                af[mt][1] = As[ka * AST + m + 8];
                af[mt][2] = As[(ka + 4) * AST + m];
                af[mt][3] = As[(ka + 4) * AST + m + 8];
            }
            #pragma unroll
            for (int nt = 0; nt < 4; nt++) {
                const int n = wn + nt * 8 + gr;
                const uint32_t b0 = Bs[(ks + gc) * BST + n];
                const uint32_t b1 = Bs[(ks + gc + 4) * BST + n];
                #pragma unroll
                for (int mt = 0; mt < 4; mt++)
                    mma_tf32(acc[mt][nt], af[mt][0], af[mt][1], af[mt][2], af[mt][3],
                             b0, b1);
            }
        }

        if (kt + 1 < nkt) {
            // commit prefetched tile -> other stage
            uint32_t* An = Asm + (cur ^ 1) * STG_A;
            uint32_t* Bn = Bsm + (cur ^ 1) * STG_B;
            An[(ac0 + 0) * AST + ar0] = f2tf(pa0.x);
            An[(ac0 + 1) * AST + ar0] = f2tf(pa0.y);
            An[(ac0 + 2) * AST + ar0] = f2tf(pa0.z);
            An[(ac0 + 3) * AST + ar0] = f2tf(pa0.w);
            An[(ac1 + 0) * AST + ar1] = f2tf(pa1.x);
            An[(ac1 + 1) * AST + ar1] = f2tf(pa1.y);
            An[(ac1 + 2) * AST + ar1] = f2tf(pa1.z);
            An[(ac1 + 3) * AST + ar1] = f2tf(pa1.w);
            uint4 u0, u1;
            u0.x = f2tf(pb0.x); u0.y = f2tf(pb0.y); u0.z = f2tf(pb0.z); u0.w = f2tf(pb0.w);
            u1.x = f2tf(pb1.x); u1.y = f2tf(pb1.y); u1.z = f2tf(pb1.z); u1.w = f2tf(pb1.w);
            *(uint4*)&Bn[br0 * BST + bc0] = u0;
            *(uint4*)&Bn[br1 * BST + bc1] = u1;
            __syncthreads();

            if (kt + 2 < nkt) {  // prefetch tile kt+2 (hidden under next mma)
                const int k0 = (kt + 2) * BK;
                pa0 = *(const float4*)(Ab + (size_t)ar0 * K + k0 + ac0);
                pa1 = *(const float4*)(Ab + (size_t)ar1 * K + k0 + ac1);
                pb0 = *(const float4*)(Bb + (size_t)(k0 + br0) * N + bc0);
                pb1 = *(const float4*)(Bb + (size_t)(k0 + br1) * N + bc1);
            }
        }
    }

    float2 bv[4];
    #pragma unroll
    for (int nt = 0; nt < 4; nt++)
        bv[nt] = *(const float2*)(bias + n0 + wn + nt * 8 + gc * 2);

    #pragma unroll
    for (int mt = 0; mt < 4; mt++) {
        const int gm = m0 + wm + mt * 16 + gr;
        #pragma unroll
        for (int nt = 0; nt < 4; nt++) {
            const int gn = n0 + wn + nt * 8 + gc * 2;
            float2 o0, o1;
            o0.x = acc[mt][nt][0] + bv[nt].x;
            o0.y = acc[mt][nt][1] + bv[nt].y;
            o1.x = acc[mt][nt][2] + bv[nt].x;
            o1.y = acc[mt][nt][3] + bv[nt].y;
            if (EPI == 1) {
                o0.x = fmaxf(o0.x, 0.f); o0.y = fmaxf(o0.y, 0.f);
                o1.x = fmaxf(o1.x, 0.f); o1.y = fmaxf(o1.y, 0.f);
            }
            if (EPI == 2) {
                const float2 r0 = *(const float2*)(R + (size_t)gm * N + gn);
                const float2 r1 = *(const float2*)(R + (size_t)(gm + 8) * N + gn);
                o0.x += r0.x; o0.y += r0.y;
                o1.x += r1.x; o1.y += r1.y;
            }
            *(float2*)(C + (size_t)gm * N + gn)       = o0;
            *(float2*)(C + (size_t)(gm + 8) * N + gn) = o1;
        }
    }
}

template<int EPI>
__global__ __launch_bounds__(256, 2) void tgemm_kernel(
    const float* __restrict__ A, const float* __restrict__ B,
    const float* __restrict__ bias, const float* __restrict__ R,
    float* __restrict__ C, int M, int N, int K)
{
    extern __shared__ uint32_t smg[];
    tgemm_body<EPI>(A, B, bias, R, C, M, N, K,
                    blockIdx.y * BM, blockIdx.x * BN, smg, smg + 2 * STG_A);
}

__global__ __launch_bounds__(256, 2) void qkv_kernel(
    const float* __restrict__ A,
    const float* __restrict__ B0, const float* __restrict__ B1, const float* __restrict__ B2,
    const float* __restrict__ b0, const float* __restrict__ b1, const float* __restrict__ b2,
    float* __restrict__ C0, float* __restrict__ C1, float* __restrict__ C2)
{
    extern __shared__ uint32_t smg[];
    const float* B = (blockIdx.z == 0) ? B0 : (blockIdx.z == 1) ? B1 : B2;
    const float* bb = (blockIdx.z == 0) ? b0 : (blockIdx.z == 1) ? b1 : b2;
    float* C = (blockIdx.z == 0) ? C0 : (blockIdx.z == 1) ? C1 : C2;
    tgemm_body<0>(A, B, bb, nullptr, C, MTOT, EMB, EMB,
                  blockIdx.y * BM, blockIdx.x * BN, smg, smg + 2 * STG_A);
}

// ---------------------------------------------------------------------------
// Flash-attention v3: tf32 tensor cores + log2-domain online softmax.
// (unchanged from round 9 — proven at ~310 us)
// ---------------------------------------------------------------------------
#define AQT 128
#define AKT 64
#define QP 68    // 68 mod 32 = 4
#define KP 72    // 72 mod 32 = 8
#define ATT_SMEM ((128*QP + 64*KP + 64*KP + 128*QP) * 4)   // 106496 B
#define QSCALE 0.18033688011112042f   // 0.125 * log2(e)

__global__ __launch_bounds__(256, 1) void attn3_kernel(
    const float* __restrict__ Q, const float* __restrict__ Km,
    const float* __restrict__ Vm, float* __restrict__ O)
{
    extern __shared__ uint32_t smu[];
    uint32_t* sQ = smu;
    uint32_t* sK = sQ + 128 * QP;
    uint32_t* sV = sK + 64 * KP;
    uint32_t* sP = sV + 64 * KP;

    const int bh = blockIdx.y;
    const int b  = bh / HEADS;
    const int h  = bh % HEADS;
    const int q0 = blockIdx.x * AQT;
    const int tid  = threadIdx.x;
    const int warp = tid >> 5;
    const int lane = tid & 31;
    const int gr   = lane >> 2;
    const int gc   = lane & 3;
    const int wq0  = warp * 16;
    uint32_t* sPw = sP + warp * 16 * QP;

    const size_t base = ((size_t)b * SEQ) * EMB + (size_t)h * HDIM;
    const float* Qb = Q  + base;
    const float* Kb = Km + base;
    const float* Vb = Vm + base;

    #pragma unroll
    for (int t = 0; t < 8; t++) {
        int idx = tid + t * 256;
        int qr = idx >> 4, c4 = (idx & 15) * 4;
        float4 v = *(const float4*)(Qb + (size_t)(q0 + qr) * EMB + c4);
        sQ[qr * QP + c4 + 0] = f2tf(v.x * QSCALE);
        sQ[qr * QP + c4 + 1] = f2tf(v.y * QSCALE);
        sQ[qr * QP + c4 + 2] = f2tf(v.z * QSCALE);
        sQ[qr * QP + c4 + 3] = f2tf(v.w * QSCALE);
    }

    float m0 = -1e30f, m1 = -1e30f, l0 = 0.f, l1 = 0.f;
    float oacc[8][4];
    #pragma unroll
    for (int nt = 0; nt < 8; nt++)
        #pragma unroll
        for (int r = 0; r < 4; r++) oacc[nt][r] = 0.f;

    const int kr0 = tid >> 4;
    const int kc4 = (tid & 15) * 4;
    float4 pk[4], pv[4];
    #pragma unroll
    for (int t = 0; t < 4; t++) {
        size_t goff = (size_t)(kr0 + t * 16) * EMB + kc4;
        pk[t] = *(const float4*)(Kb + goff);
        pv[t] = *(const float4*)(Vb + goff);
    }

    for (int kt = 0; kt < SEQ / AKT; kt++) {
        #pragma unroll
        for (int t = 0; t < 4; t++) {
            int kr = kr0 + t * 16;
            sK[(kc4 + 0) * KP + kr] = f2tf(pk[t].x);
            sK[(kc4 + 1) * KP + kr] = f2tf(pk[t].y);
            sK[(kc4 + 2) * KP + kr] = f2tf(pk[t].z);
            sK[(kc4 + 3) * KP + kr] = f2tf(pk[t].w);
            uint4 u;
            u.x = f2tf(pv[t].x); u.y = f2tf(pv[t].y);
            u.z = f2tf(pv[t].z); u.w = f2tf(pv[t].w);
            *(uint4*)&sV[kr * KP + kc4] = u;
        }
        __syncthreads();

        if (kt + 1 < SEQ / AKT) {
            const size_t tb = (size_t)(kt + 1) * AKT * EMB;
            #pragma unroll
            for (int t = 0; t < 4; t++) {
                size_t goff = tb + (size_t)(kr0 + t * 16) * EMB + kc4;
                pk[t] = *(const float4*)(Kb + goff);
                pv[t] = *(const float4*)(Vb + goff);
            }
        }

        float sacc[8][4];
        #pragma unroll
        for (int nt = 0; nt < 8; nt++)
            #pragma unroll
            for (int r = 0; r < 4; r++) sacc[nt][r] = 0.f;

        #pragma unroll
        for (int ks = 0; ks < 8; ks++) {
            const int ka = ks * 8 + gc;
            const uint32_t a0 = sQ[(wq0 + gr) * QP + ka];
            const uint32_t a1 = sQ[(wq0 + gr + 8) * QP + ka];
            const uint32_t a2 = sQ[(wq0 + gr) * QP + ka + 4];
            const uint32_t a3 = sQ[(wq0 + gr + 8) * QP + ka + 4];
            #pragma unroll
            for (int nt = 0; nt < 8; nt++) {
                const uint32_t b0 = sK[ka * KP + nt * 8 + gr];
                const uint32_t b1 = sK[(ka + 4) * KP + nt * 8 + gr];
                mma_tf32(sacc[nt], a0, a1, a2, a3, b0, b1);
            }
        }

        float t0 = -1e30f, t1 = -1e30f;
        #pragma unroll
        for (int nt = 0; nt < 8; nt++) {
            t0 = fmaxf(t0, fmaxf(sacc[nt][0], sacc[nt][1]));
            t1 = fmaxf(t1, fmaxf(sacc[nt][2], sacc[nt][3]));
        }
        t0 = fmaxf(t0, __shfl_xor_sync(0xffffffffu, t0, 1));
        t0 = fmaxf(t0, __shfl_xor_sync(0xffffffffu, t0, 2));
        t1 = fmaxf(t1, __shfl_xor_sync(0xffffffffu, t1, 1));
        t1 = fmaxf(t1, __shfl_xor_sync(0xffffffffu, t1, 2));
        const float nm0 = fmaxf(m0, t0);
        const float nm1 = fmaxf(m1, t1);
        const float c0 = ex2(m0 - nm0);
        const float c1 = ex2(m1 - nm1);
        float ps0 = 0.f, ps1 = 0.f;
        #pragma unroll
        for (int nt = 0; nt < 8; nt++) {
            const float p00 = ex2(sacc[nt][0] - nm0);
            const float p01 = ex2(sacc[nt][1] - nm0);
            const float p10 = ex2(sacc[nt][2] - nm1);
            const float p11 = ex2(sacc[nt][3] - nm1);
            ps0 += p00 + p01;
            ps1 += p10 + p11;
            sPw[gr * QP + nt * 8 + gc * 2]           = f2tf(p00);
            sPw[gr * QP + nt * 8 + gc * 2 + 1]       = f2tf(p01);
            sPw[(gr + 8) * QP + nt * 8 + gc * 2]     = f2tf(p10);
            sPw[(gr + 8) * QP + nt * 8 + gc * 2 + 1] = f2tf(p11);
        }
        ps0 += __shfl_xor_sync(0xffffffffu, ps0, 1);
        ps0 += __shfl_xor_sync(0xffffffffu, ps0, 2);
        ps1 += __shfl_xor_sync(0xffffffffu, ps1, 1);
        ps1 += __shfl_xor_sync(0xffffffffu, ps1, 2);
        l0 = l0 * c0 + ps0;
        l1 = l1 * c1 + ps1;
        m0 = nm0; m1 = nm1;
        #pragma unroll
        for (int nt = 0; nt < 8; nt++) {
            oacc[nt][0] *= c0; oacc[nt][1] *= c0;
            oacc[nt][2] *= c1; oacc[nt][3] *= c1;
        }
        __syncwarp();

        #pragma unroll
        for (int ks = 0; ks < 8; ks++) {
            const int kk = ks * 8 + gc;
            const uint32_t a0 = sPw[gr * QP + kk];
            const uint32_t a1 = sPw[(gr + 8) * QP + kk];
            const uint32_t a2 = sPw[gr * QP + kk + 4];
            const uint32_t a3 = sPw[(gr + 8) * QP + kk + 4];
            #pragma unroll
            for (int nt = 0; nt < 8; nt++) {
                const uint32_t b0 = sV[kk * KP + nt * 8 + gr];
                const uint32_t b1 = sV[(kk + 4) * KP + nt * 8 + gr];
                mma_tf32(oacc[nt], a0, a1, a2, a3, b0, b1);
            }
        }
        __syncthreads();
    }

    const float inv0 = 1.0f / l0;
    const float inv1 = 1.0f / l1;
    float* O0 = O + base + (size_t)(q0 + wq0 + gr) * EMB;
    float* O1 = O + base + (size_t)(q0 + wq0 + gr + 8) * EMB;
    #pragma unroll
    for (int nt = 0; nt < 8; nt++) {
        const int cn = nt * 8 + gc * 2;
        float2 x0, x1;
        x0.x = oacc[nt][0] * inv0; x0.y = oacc[nt][1] * inv0;
        x1.x = oacc[nt][2] * inv1; x1.y = oacc[nt][3] * inv1;
        *(float2*)(O0 + cn) = x0;
        *(float2*)(O1 + cn) = x1;
    }
}

// ---------------------------------------------------------------------------
// Launch
// ---------------------------------------------------------------------------
extern "C" void kernel_launch(void* const* d_in, const int* in_sizes, int n_in,
                              void* d_out, int out_size)
{
    const float* x    = (const float*)d_in[0];
    const float* ln1g = (const float*)d_in[1];
    const float* ln1b = (const float*)d_in[2];
    const float* ln2g = (const float*)d_in[3];
    const float* ln2b = (const float*)d_in[4];
    const float* Wq   = (const float*)d_in[5];
    const float* bq   = (const float*)d_in[6];
    const float* Wk   = (const float*)d_in[7];
    const float* bk   = (const float*)d_in[8];
    const float* Wv   = (const float*)d_in[9];
    const float* bv   = (const float*)d_in[10];
    const float* Wo   = (const float*)d_in[11];
    const float* bo   = (const float*)d_in[12];
    const float* W1   = (const float*)d_in[13];
    const float* b1   = (const float*)d_in[14];
    const float* W2   = (const float*)d_in[15];
    const float* b2   = (const float*)d_in[16];
    float* out = (float*)d_out;

    float *xn, *q, *k, *v, *att, *x2, *xn2, *hb;
    cudaGetSymbolAddress((void**)&xn,  g_xn);
    cudaGetSymbolAddress((void**)&q,   g_q);
    cudaGetSymbolAddress((void**)&k,   g_k);
    cudaGetSymbolAddress((void**)&v,   g_v);
    cudaGetSymbolAddress((void**)&att, g_att);
    cudaGetSymbolAddress((void**)&x2,  g_x2);
    cudaGetSymbolAddress((void**)&xn2, g_xn2);
    cudaGetSymbolAddress((void**)&hb,  g_h);

    cudaFuncSetAttribute(attn3_kernel,
                         cudaFuncAttributeMaxDynamicSharedMemorySize, ATT_SMEM);
    cudaFuncSetAttribute(tgemm_kernel<1>,
                         cudaFuncAttributeMaxDynamicSharedMemorySize, GEMM_SMEM);
    cudaFuncSetAttribute(tgemm_kernel<2>,
                         cudaFuncAttributeMaxDynamicSharedMemorySize, GEMM_SMEM);
    cudaFuncSetAttribute(qkv_kernel,
                         cudaFuncAttributeMaxDynamicSharedMemorySize, GEMM_SMEM);

    const dim3 blk(256);
    const dim3 gQKV(EMB / BN, MTOT / BM, 3);
    const dim3 gEmb(EMB / BN, MTOT / BM);
    const dim3 gMlp(MLPH / BN, MTOT / BM);
    const dim3 gAtt(SEQ / AQT, BATCH * HEADS);

    // 1. LN1
    ln_kernel<<<MTOT, blk>>>(x, ln1g, ln1b, xn);
    // 2. QKV projections (fused launch, tf32 tensor cores, double-buffered)
    qkv_kernel<<<gQKV, blk, GEMM_SMEM>>>(xn, Wq, Wk, Wv, bq, bk, bv, q, k, v);
    // 3. Attention (tf32 tensor cores)
    attn3_kernel<<<gAtt, blk, ATT_SMEM>>>(q, k, v, att);
    // 4. Output projection + residual
    tgemm_kernel<2><<<gEmb, blk, GEMM_SMEM>>>(att, Wo, bo, x, x2, MTOT, EMB, EMB);
    // 5. LN2
    ln_kernel<<<MTOT, blk>>>(x2, ln2g, ln2b, xn2);
    // 6. MLP up + ReLU
    tgemm_kernel<1><<<gMlp, blk, GEMM_SMEM>>>(xn2, W1, b1, nullptr, hb, MTOT, MLPH, EMB);
    // 7. MLP down + residual -> output
    tgemm_kernel<2><<<gEmb, blk, GEMM_SMEM>>>(hb, W2, b2, x2, out, MTOT, EMB, MLPH);
}

// round 13
// speedup vs baseline: 1.0913x; 1.0887x over previous
#include <cuda_runtime.h>
#include <cuda_bf16.h>
#include <cstdint>

// ---------------------------------------------------------------------------
// Problem constants
// ---------------------------------------------------------------------------
#define BATCH 2
#define SEQ   2048
#define EMB   1024
#define HEADS 16
#define HDIM  64
#define MLPH  4096
#define MTOT  (BATCH * SEQ)   // 4096 rows

// ---------------------------------------------------------------------------
// Scratch (device globals: allocation-free)
// Activation buffers consumed as GEMM-A are stored as tf32 bit patterns.
// ---------------------------------------------------------------------------
__device__ uint32_t g_xn [MTOT * EMB];    // LN1 out (tf32)
__device__ float    g_q  [MTOT * EMB];
__device__ float    g_k  [MTOT * EMB];
__device__ float    g_v  [MTOT * EMB];
__device__ uint32_t g_att[MTOT * EMB];    // attn out (tf32)
__device__ float    g_x2 [MTOT * EMB];
__device__ uint32_t g_xn2[MTOT * EMB];    // LN2 out (tf32)
__device__ uint32_t g_h  [MTOT * MLPH];   // ReLU out (tf32)
// tf32-converted weights, natural [K][N] layout
__device__ uint32_t g_wq32[EMB * EMB];
__device__ uint32_t g_wk32[EMB * EMB];
__device__ uint32_t g_wv32[EMB * EMB];
__device__ uint32_t g_wo32[EMB * EMB];
__device__ uint32_t g_w132[EMB * MLPH];
__device__ uint32_t g_w232[MLPH * EMB];

// ---------------------------------------------------------------------------
// Helpers
// ---------------------------------------------------------------------------
__device__ __forceinline__ uint32_t f2tf(float f) {
    uint32_t u;
    asm("cvt.rna.tf32.f32 %0, %1;" : "=r"(u) : "f"(f));
    return u;
}
__device__ __forceinline__ float ex2(float x) {
    float r;
    asm("ex2.approx.f32 %0, %1;" : "=f"(r) : "f"(x));
    return r;
}
__device__ __forceinline__ void mma_tf32(
    float* c, uint32_t a0, uint32_t a1, uint32_t a2, uint32_t a3,
    uint32_t b0, uint32_t b1)
{
    asm volatile(
        "mma.sync.aligned.m16n8k8.row.col.f32.tf32.tf32.f32 "
        "{%0,%1,%2,%3}, {%4,%5,%6,%7}, {%8,%9}, {%0,%1,%2,%3};"
        : "+f"(c[0]), "+f"(c[1]), "+f"(c[2]), "+f"(c[3])
        : "r"(a0), "r"(a1), "r"(a2), "r"(a3), "r"(b0), "r"(b1));
}
__device__ __forceinline__ uint32_t smem_u32(const void* p) {
    uint32_t a;
    asm("{ .reg .u64 t; cvta.to.shared.u64 t, %1; cvt.u32.u64 %0, t; }"
        : "=r"(a) : "l"(p));
    return a;
}
__device__ __forceinline__ void cpa16(uint32_t dst, const void* src) {
    asm volatile("cp.async.cg.shared.global [%0], [%1], 16;"
                 :: "r"(dst), "l"(src) : "memory");
}
#define CP_COMMIT() asm volatile("cp.async.commit_group;" ::: "memory")
#define CP_WAIT2()  asm volatile("cp.async.wait_group 2;" ::: "memory")

// ---------------------------------------------------------------------------
// LayerNorm: one block per row of 1024, 256 threads; output = tf32 bits
// ---------------------------------------------------------------------------
__global__ __launch_bounds__(256) void ln_kernel(
    const float* __restrict__ x, const float* __restrict__ g,
    const float* __restrict__ b, uint32_t* __restrict__ y)
{
    int row = blockIdx.x;
    int tid = threadIdx.x;
    const float4 v = ((const float4*)(x + (size_t)row * EMB))[tid];

    float s  = v.x + v.y + v.z + v.w;
    float ss = v.x * v.x + v.y * v.y + v.z * v.z + v.w * v.w;
    #pragma unroll
    for (int o = 16; o; o >>= 1) {
        s  += __shfl_xor_sync(0xffffffffu, s,  o);
        ss += __shfl_xor_sync(0xffffffffu, ss, o);
    }
    __shared__ float rs[8], rss[8];
    int w = tid >> 5, lane = tid & 31;
    if (lane == 0) { rs[w] = s; rss[w] = ss; }
    __syncthreads();
    s = 0.f; ss = 0.f;
    #pragma unroll
    for (int i = 0; i < 8; i++) { s += rs[i]; ss += rss[i]; }

    const float mean = s * (1.0f / EMB);
    const float var  = ss * (1.0f / EMB) - mean * mean;
    const float rstd = rsqrtf(var + 1e-5f);

    const float4 gv = ((const float4*)g)[tid];
    const float4 bv = ((const float4*)b)[tid];
    uint4 o;
    o.x = f2tf((v.x - mean) * rstd * gv.x + bv.x);
    o.y = f2tf((v.y - mean) * rstd * gv.y + bv.y);
    o.z = f2tf((v.z - mean) * rstd * gv.z + bv.z);
    o.w = f2tf((v.w - mean) * rstd * gv.w + bv.w);
    ((uint4*)(y + (size_t)row * EMB))[tid] = o;
}

// ---------------------------------------------------------------------------
// Elementwise weight convert fp32 -> tf32 bits (layout preserved [K][N])
// ---------------------------------------------------------------------------
__global__ __launch_bounds__(256) void wconv_kernel(
    const float* __restrict__ W, uint32_t* __restrict__ Wt, int n4)
{
    int i = blockIdx.x * 256 + threadIdx.x;
    if (i < n4) {
        const float4 v = ((const float4*)W)[i];
        uint4 u;
        u.x = f2tf(v.x); u.y = f2tf(v.y); u.z = f2tf(v.z); u.w = f2tf(v.w);
        ((uint4*)Wt)[i] = u;
    }
}

// ---------------------------------------------------------------------------
// TF32 GEMM, cp.async 4-stage pipeline, pre-converted tf32 operands.
// C[M,N] = A[M,K] @ B[K,N] + bias (+relu->tf32 / +residual)
// CTA 128x256, BK=16, 256 threads (8 warps), warp tile 64x64.
// smem stage: A [128][36] row-major, B [16][264] n-major (bank-conflict-free).
// EPI: 0 = bias -> fp32, 1 = bias+relu -> tf32 bits, 2 = bias+residual -> fp32
// ---------------------------------------------------------------------------
#define BM 128
#define BN 256
#define BK 16
#define AP 36
#define BP 264
#define ASTG (BM * AP)              // 4608 words
#define BSTG (BK * BP)              // 4224 words
#define STGW (ASTG + BSTG)          // 8832 words
#define STAGES 4
#define CP_SMEM (STAGES * STGW * 4) // 141312 B

template<int EPI>
__device__ __forceinline__ void cpgemm_body(
    const uint32_t* __restrict__ A, const uint32_t* __restrict__ B,
    const float* __restrict__ bias, const float* __restrict__ R,
    float* __restrict__ C, int M, int N, int K, int m0, int n0)
{
    extern __shared__ uint32_t smc[];
    const uint32_t sbase = smem_u32(smc);
    const int tid  = threadIdx.x;
    const int warp = tid >> 5;
    const int lane = tid & 31;
    const int gr   = lane >> 2;
    const int gc   = lane & 3;
    const int wm   = (warp & 1) * 64;
    const int wn   = (warp >> 1) * 64;

    // A loader: 512 chunks (128 rows x 4), 2/thread
    const int arow0 = tid >> 2,          ac0 = (tid & 3) * 4;
    const int arow1 = (tid + 256) >> 2,  ac1 = ((tid + 256) & 3) * 4;
    // B loader: 1024 chunks (16 rows x 64), 4/thread
    const int brow[4] = { tid >> 6, (tid + 256) >> 6, (tid + 512) >> 6, (tid + 768) >> 6 };
    const int bcw     = (tid & 63) * 4;

    const uint32_t* Ab = A + (size_t)m0 * K;
    const uint32_t* Bb = B + n0;

    // per-thread smem byte dest offsets within a stage
    const uint32_t dA0 = (uint32_t)(arow0 * AP + ac0) * 4;
    const uint32_t dA1 = (uint32_t)(arow1 * AP + ac1) * 4;
    uint32_t dB[4];
    #pragma unroll
    for (int t = 0; t < 4; t++)
        dB[t] = (uint32_t)(ASTG + brow[t] * BP + bcw) * 4;

    const int nkt = K / BK;

    // prologue: issue stages 0..2
    #pragma unroll
    for (int s = 0; s < STAGES - 1; s++) {
        if (s < nkt) {
            const uint32_t sb = sbase + s * STGW * 4;
            const int k0 = s * BK;
            cpa16(sb + dA0, Ab + (size_t)arow0 * K + k0 + ac0);
            cpa16(sb + dA1, Ab + (size_t)arow1 * K + k0 + ac1);
            #pragma unroll
            for (int t = 0; t < 4; t++)
                cpa16(sb + dB[t], Bb + (size_t)(k0 + brow[t]) * N + bcw);
        }
        CP_COMMIT();
    }

    float acc[4][8][4];
    #pragma unroll
    for (int mt = 0; mt < 4; mt++)
        #pragma unroll
        for (int nt = 0; nt < 8; nt++)
            #pragma unroll
            for (int r = 0; r < 4; r++) acc[mt][nt][r] = 0.f;

    for (int kt = 0; kt < nkt; kt++) {
        CP_WAIT2();
        __syncthreads();

        // issue stage kt+3 into slot (kt+3)%4 == (kt-1)%4 (safe post-sync)
        if (kt + STAGES - 1 < nkt) {
            const uint32_t sb = sbase + ((kt + STAGES - 1) % STAGES) * STGW * 4;
            const int k0 = (kt + STAGES - 1) * BK;
            cpa16(sb + dA0, Ab + (size_t)arow0 * K + k0 + ac0);
            cpa16(sb + dA1, Ab + (size_t)arow1 * K + k0 + ac1);
            #pragma unroll
            for (int t = 0; t < 4; t++)
                cpa16(sb + dB[t], Bb + (size_t)(k0 + brow[t]) * N + bcw);
        }
        CP_COMMIT();

        const uint32_t* As = smc + (kt % STAGES) * STGW;
        const uint32_t* Bs = As + ASTG;

        #pragma unroll
        for (int ks = 0; ks < BK; ks += 8) {
            uint32_t af[4][4];
            #pragma unroll
            for (int mt = 0; mt < 4; mt++) {
                const int m = wm + mt * 16 + gr;
                const int ka = ks + gc;
                af[mt][0] = As[m * AP + ka];
                af[mt][1] = As[(m + 8) * AP + ka];
                af[mt][2] = As[m * AP + ka + 4];
                af[mt][3] = As[(m + 8) * AP + ka + 4];
            }
            #pragma unroll
            for (int nt = 0; nt < 8; nt++) {
                const int n = wn + nt * 8 + gr;
                const uint32_t b0 = Bs[(ks + gc) * BP + n];
                const uint32_t b1 = Bs[(ks + gc + 4) * BP + n];
                #pragma unroll
                for (int mt = 0; mt < 4; mt++)
                    mma_tf32(acc[mt][nt], af[mt][0], af[mt][1], af[mt][2], af[mt][3],
                             b0, b1);
            }
        }
    }

    // epilogue
    float2 bv[8];
    #pragma unroll
    for (int nt = 0; nt < 8; nt++)
        bv[nt] = *(const float2*)(bias + n0 + wn + nt * 8 + gc * 2);

    #pragma unroll
    for (int mt = 0; mt < 4; mt++) {
        const int gm = m0 + wm + mt * 16 + gr;
        #pragma unroll
        for (int nt = 0; nt < 8; nt++) {
            const int gn = n0 + wn + nt * 8 + gc * 2;
            float2 o0, o1;
            o0.x = acc[mt][nt][0] + bv[nt].x;
            o0.y = acc[mt][nt][1] + bv[nt].y;
            o1.x = acc[mt][nt][2] + bv[nt].x;
            o1.y = acc[mt][nt][3] + bv[nt].y;
            if (EPI == 1) {
                o0.x = fmaxf(o0.x, 0.f); o0.y = fmaxf(o0.y, 0.f);
                o1.x = fmaxf(o1.x, 0.f); o1.y = fmaxf(o1.y, 0.f);
                uint2 u0, u1;
                u0.x = f2tf(o0.x); u0.y = f2tf(o0.y);
                u1.x = f2tf(o1.x); u1.y = f2tf(o1.y);
                uint32_t* Cu = (uint32_t*)C;
                *(uint2*)(Cu + (size_t)gm * N + gn)       = u0;
                *(uint2*)(Cu + (size_t)(gm + 8) * N + gn) = u1;
            } else {
                if (EPI == 2) {
                    const float2 r0 = *(const float2*)(R + (size_t)gm * N + gn);
                    const float2 r1 = *(const float2*)(R + (size_t)(gm + 8) * N + gn);
                    o0.x += r0.x; o0.y += r0.y;
                    o1.x += r1.x; o1.y += r1.y;
                }
                *(float2*)(C + (size_t)gm * N + gn)       = o0;
                *(float2*)(C + (size_t)(gm + 8) * N + gn) = o1;
            }
        }
    }
}

template<int EPI>
__global__ __launch_bounds__(256, 1) void cpgemm_kernel(
    const uint32_t* __restrict__ A, const uint32_t* __restrict__ B,
    const float* __restrict__ bias, const float* __restrict__ R,
    float* __restrict__ C, int M, int N, int K)
{
    cpgemm_body<EPI>(A, B, bias, R, C, M, N, K,
                     blockIdx.y * BM, blockIdx.x * BN);
}

__global__ __launch_bounds__(256, 1) void qkvcp_kernel(
    const uint32_t* __restrict__ A,
    const uint32_t* __restrict__ B0, const uint32_t* __restrict__ B1,
    const uint32_t* __restrict__ B2,
    const float* __restrict__ b0, const float* __restrict__ b1,
    const float* __restrict__ b2,
    float* __restrict__ C0, float* __restrict__ C1, float* __restrict__ C2)
{
    const uint32_t* B = (blockIdx.z == 0) ? B0 : (blockIdx.z == 1) ? B1 : B2;
    const float* bb = (blockIdx.z == 0) ? b0 : (blockIdx.z == 1) ? b1 : b2;
    float* C = (blockIdx.z == 0) ? C0 : (blockIdx.z == 1) ? C1 : C2;
    cpgemm_body<0>(A, B, bb, nullptr, C, MTOT, EMB, EMB,
                   blockIdx.y * BM, blockIdx.x * BN);
}

// ---------------------------------------------------------------------------
// Flash-attention v3: tf32 tensor cores + log2-domain online softmax.
// Output written as tf32 bits (consumed by Wo GEMM as A).
// ---------------------------------------------------------------------------
#define AQT 128
#define AKT 64
#define QP 68
#define KP 72
#define ATT_SMEM ((128*QP + 64*KP + 64*KP + 128*QP) * 4)   // 106496 B
#define QSCALE 0.18033688011112042f   // 0.125 * log2(e)

__global__ __launch_bounds__(256, 1) void attn3_kernel(
    const float* __restrict__ Q, const float* __restrict__ Km,
    const float* __restrict__ Vm, uint32_t* __restrict__ O)
{
    extern __shared__ uint32_t smu[];
    uint32_t* sQ = smu;
    uint32_t* sK = sQ + 128 * QP;
    uint32_t* sV = sK + 64 * KP;
    uint32_t* sP = sV + 64 * KP;

    const int bh = blockIdx.y;
    const int b  = bh / HEADS;
    const int h  = bh % HEADS;
    const int q0 = blockIdx.x * AQT;
    const int tid  = threadIdx.x;
    const int warp = tid >> 5;
    const int lane = tid & 31;
    const int gr   = lane >> 2;
    const int gc   = lane & 3;
    const int wq0  = warp * 16;
    uint32_t* sPw = sP + warp * 16 * QP;

    const size_t base = ((size_t)b * SEQ) * EMB + (size_t)h * HDIM;
    const float* Qb = Q  + base;
    const float* Kb = Km + base;
    const float* Vb = Vm + base;

    #pragma unroll
    for (int t = 0; t < 8; t++) {
        int idx = tid + t * 256;
        int qr = idx >> 4, c4 = (idx & 15) * 4;
        float4 v = *(const float4*)(Qb + (size_t)(q0 + qr) * EMB + c4);
        sQ[qr * QP + c4 + 0] = f2tf(v.x * QSCALE);
        sQ[qr * QP + c4 + 1] = f2tf(v.y * QSCALE);
        sQ[qr * QP + c4 + 2] = f2tf(v.z * QSCALE);
        sQ[qr * QP + c4 + 3] = f2tf(v.w * QSCALE);
    }

    float m0 = -1e30f, m1 = -1e30f, l0 = 0.f, l1 = 0.f;
    float oacc[8][4];
    #pragma unroll
    for (int nt = 0; nt < 8; nt++)
        #pragma unroll
        for (int r = 0; r < 4; r++) oacc[nt][r] = 0.f;

    const int kr0 = tid >> 4;
    const int kc4 = (tid & 15) * 4;
    float4 pk[4], pv[4];
    #pragma unroll
    for (int t = 0; t < 4; t++) {
        size_t goff = (size_t)(kr0 + t * 16) * EMB + kc4;
        pk[t] = *(const float4*)(Kb + goff);
        pv[t] = *(const float4*)(Vb + goff);
    }

    for (int kt = 0; kt < SEQ / AKT; kt++) {
        #pragma unroll
        for (int t = 0; t < 4; t++) {
            int kr = kr0 + t * 16;
            sK[(kc4 + 0) * KP + kr] = f2tf(pk[t].x);
            sK[(kc4 + 1) * KP + kr] = f2tf(pk[t].y);
            sK[(kc4 + 2) * KP + kr] = f2tf(pk[t].z);
            sK[(kc4 + 3) * KP + kr] = f2tf(pk[t].w);
            uint4 u;
            u.x = f2tf(pv[t].x); u.y = f2tf(pv[t].y);
            u.z = f2tf(pv[t].z); u.w = f2tf(pv[t].w);
            *(uint4*)&sV[kr * KP + kc4] = u;
        }
        __syncthreads();

        if (kt + 1 < SEQ / AKT) {
            const size_t tb = (size_t)(kt + 1) * AKT * EMB;
            #pragma unroll
            for (int t = 0; t < 4; t++) {
                size_t goff = tb + (size_t)(kr0 + t * 16) * EMB + kc4;
                pk[t] = *(const float4*)(Kb + goff);
                pv[t] = *(const float4*)(Vb + goff);
            }
        }

        float sacc[8][4];
        #pragma unroll
        for (int nt = 0; nt < 8; nt++)
            #pragma unroll
            for (int r = 0; r < 4; r++) sacc[nt][r] = 0.f;

        #pragma unroll
        for (int ks = 0; ks < 8; ks++) {
            const int ka = ks * 8 + gc;
            const uint32_t a0 = sQ[(wq0 + gr) * QP + ka];
            const uint32_t a1 = sQ[(wq0 + gr + 8) * QP + ka];
            const uint32_t a2 = sQ[(wq0 + gr) * QP + ka + 4];
            const uint32_t a3 = sQ[(wq0 + gr + 8) * QP + ka + 4];
            #pragma unroll
            for (int nt = 0; nt < 8; nt++) {
                const uint32_t b0 = sK[ka * KP + nt * 8 + gr];
                const uint32_t b1 = sK[(ka + 4) * KP + nt * 8 + gr];
                mma_tf32(sacc[nt], a0, a1, a2, a3, b0, b1);
            }
        }

        float t0 = -1e30f, t1 = -1e30f;
        #pragma unroll
        for (int nt = 0; nt < 8; nt++) {
            t0 = fmaxf(t0, fmaxf(sacc[nt][0], sacc[nt][1]));
            t1 = fmaxf(t1, fmaxf(sacc[nt][2], sacc[nt][3]));
        }
        t0 = fmaxf(t0, __shfl_xor_sync(0xffffffffu, t0, 1));
        t0 = fmaxf(t0, __shfl_xor_sync(0xffffffffu, t0, 2));
        t1 = fmaxf(t1, __shfl_xor_sync(0xffffffffu, t1, 1));
        t1 = fmaxf(t1, __shfl_xor_sync(0xffffffffu, t1, 2));
        const float nm0 = fmaxf(m0, t0);
        const float nm1 = fmaxf(m1, t1);
        const float c0 = ex2(m0 - nm0);
        const float c1 = ex2(m1 - nm1);
        float ps0 = 0.f, ps1 = 0.f;
        #pragma unroll
        for (int nt = 0; nt < 8; nt++) {
            const float p00 = ex2(sacc[nt][0] - nm0);
            const float p01 = ex2(sacc[nt][1] - nm0);
            const float p10 = ex2(sacc[nt][2] - nm1);
            const float p11 = ex2(sacc[nt][3] - nm1);
            ps0 += p00 + p01;
            ps1 += p10 + p11;
            sPw[gr * QP + nt * 8 + gc * 2]           = f2tf(p00);
            sPw[gr * QP + nt * 8 + gc * 2 + 1]       = f2tf(p01);
            sPw[(gr + 8) * QP + nt * 8 + gc * 2]     = f2tf(p10);
            sPw[(gr + 8) * QP + nt * 8 + gc * 2 + 1] = f2tf(p11);
        }
        ps0 += __shfl_xor_sync(0xffffffffu, ps0, 1);
        ps0 += __shfl_xor_sync(0xffffffffu, ps0, 2);
        ps1 += __shfl_xor_sync(0xffffffffu, ps1, 1);
        ps1 += __shfl_xor_sync(0xffffffffu, ps1, 2);
        l0 = l0 * c0 + ps0;
        l1 = l1 * c1 + ps1;
        m0 = nm0; m1 = nm1;
        #pragma unroll
        for (int nt = 0; nt < 8; nt++) {
            oacc[nt][0] *= c0; oacc[nt][1] *= c0;
            oacc[nt][2] *= c1; oacc[nt][3] *= c1;
        }
        __syncwarp();

        #pragma unroll
        for (int ks = 0; ks < 8; ks++) {
            const int kk = ks * 8 + gc;
            const uint32_t a0 = sPw[gr * QP + kk];
            const uint32_t a1 = sPw[(gr + 8) * QP + kk];
            const uint32_t a2 = sPw[gr * QP + kk + 4];
            const uint32_t a3 = sPw[(gr + 8) * QP + kk + 4];
            #pragma unroll
            for (int nt = 0; nt < 8; nt++) {
                const uint32_t b0 = sV[kk * KP + nt * 8 + gr];
                const uint32_t b1 = sV[(kk + 4) * KP + nt * 8 + gr];
                mma_tf32(oacc[nt], a0, a1, a2, a3, b0, b1);
            }
        }
        __syncthreads();
    }

    const float inv0 = 1.0f / l0;
    const float inv1 = 1.0f / l1;
    uint32_t* O0 = O + base + (size_t)(q0 + wq0 + gr) * EMB;
    uint32_t* O1 = O + base + (size_t)(q0 + wq0 + gr + 8) * EMB;
    #pragma unroll
    for (int nt = 0; nt < 8; nt++) {
        const int cn = nt * 8 + gc * 2;
        uint2 x0, x1;
        x0.x = f2tf(oacc[nt][0] * inv0); x0.y = f2tf(oacc[nt][1] * inv0);
        x1.x = f2tf(oacc[nt][2] * inv1); x1.y = f2tf(oacc[nt][3] * inv1);
        *(uint2*)(O0 + cn) = x0;
        *(uint2*)(O1 + cn) = x1;
    }
}

// ---------------------------------------------------------------------------
// Launch
// ---------------------------------------------------------------------------
extern "C" void kernel_launch(void* const* d_in, const int* in_sizes, int n_in,
                              void* d_out, int out_size)
{
    const float* x    = (const float*)d_in[0];
    const float* ln1g = (const float*)d_in[1];
    const float* ln1b = (const float*)d_in[2];
    const float* ln2g = (const float*)d_in[3];
    const float* ln2b = (const float*)d_in[4];
    const float* Wq   = (const float*)d_in[5];
    const float* bq   = (const float*)d_in[6];
    const float* Wk   = (const float*)d_in[7];
    const float* bk   = (const float*)d_in[8];
    const float* Wv   = (const float*)d_in[9];
    const float* bv   = (const float*)d_in[10];
    const float* Wo   = (const float*)d_in[11];
    const float* bo   = (const float*)d_in[12];
    const float* W1   = (const float*)d_in[13];
    const float* b1   = (const float*)d_in[14];
    const float* W2   = (const float*)d_in[15];
    const float* b2   = (const float*)d_in[16];
    float* out = (float*)d_out;

    uint32_t *xn, *att, *xn2, *hb;
    float *q, *k, *v, *x2;
    uint32_t *wq32, *wk32, *wv32, *wo32, *w132, *w232;
    cudaGetSymbolAddress((void**)&xn,  g_xn);
    cudaGetSymbolAddress((void**)&q,   g_q);
    cudaGetSymbolAddress((void**)&k,   g_k);
    cudaGetSymbolAddress((void**)&v,   g_v);
    cudaGetSymbolAddress((void**)&att, g_att);
    cudaGetSymbolAddress((void**)&x2,  g_x2);
    cudaGetSymbolAddress((void**)&xn2, g_xn2);
    cudaGetSymbolAddress((void**)&hb,  g_h);
    cudaGetSymbolAddress((void**)&wq32, g_wq32);
    cudaGetSymbolAddress((void**)&wk32, g_wk32);
    cudaGetSymbolAddress((void**)&wv32, g_wv32);
    cudaGetSymbolAddress((void**)&wo32, g_wo32);
    cudaGetSymbolAddress((void**)&w132, g_w132);
    cudaGetSymbolAddress((void**)&w232, g_w232);

    cudaFuncSetAttribute(attn3_kernel,
                         cudaFuncAttributeMaxDynamicSharedMemorySize, ATT_SMEM);
    cudaFuncSetAttribute(cpgemm_kernel<1>,
                         cudaFuncAttributeMaxDynamicSharedMemorySize, CP_SMEM);
    cudaFuncSetAttribute(cpgemm_kernel<2>,
                         cudaFuncAttributeMaxDynamicSharedMemorySize, CP_SMEM);
    cudaFuncSetAttribute(qkvcp_kernel,
                         cudaFuncAttributeMaxDynamicSharedMemorySize, CP_SMEM);

    const dim3 blk(256);
    const dim3 gEmb(EMB / BN, MTOT / BM);        // (4, 32)
    const dim3 gMlp(MLPH / BN, MTOT / BM);       // (16, 32)
    const dim3 gQKV(EMB / BN, MTOT / BM, 3);
    const dim3 gAtt(SEQ / AQT, BATCH * HEADS);

    // 0. Weight convert fp32 -> tf32 (elementwise, layout preserved)
    const int c1m = EMB * EMB / 4, c4m = EMB * MLPH / 4;
    wconv_kernel<<<(c1m + 255) / 256, blk>>>(Wq, wq32, c1m);
    wconv_kernel<<<(c1m + 255) / 256, blk>>>(Wk, wk32, c1m);
    wconv_kernel<<<(c1m + 255) / 256, blk>>>(Wv, wv32, c1m);
    wconv_kernel<<<(c1m + 255) / 256, blk>>>(Wo, wo32, c1m);
    wconv_kernel<<<(c4m + 255) / 256, blk>>>(W1, w132, c4m);
    wconv_kernel<<<(c4m + 255) / 256, blk>>>(W2, w232, c4m);

    // 1. LN1 (-> tf32)
    ln_kernel<<<MTOT, blk>>>(x, ln1g, ln1b, xn);
    // 2. QKV projections
    qkvcp_kernel<<<gQKV, blk, CP_SMEM>>>(xn, wq32, wk32, wv32, bq, bk, bv, q, k, v);
    // 3. Attention (-> tf32)
    attn3_kernel<<<gAtt, blk, ATT_SMEM>>>(q, k, v, att);
    // 4. Output projection + residual
    cpgemm_kernel<2><<<gEmb, blk, CP_SMEM>>>(att, wo32, bo, x, x2, MTOT, EMB, EMB);
    // 5. LN2 (-> tf32)
    ln_kernel<<<MTOT, blk>>>(x2, ln2g, ln2b, xn2);
    // 6. MLP up + ReLU (-> tf32)
    cpgemm_kernel<1><<<gMlp, blk, CP_SMEM>>>(xn2, w132, b1, nullptr, (float*)hb,
                                             MTOT, MLPH, EMB);
    // 7. MLP down + residual -> output
    cpgemm_kernel<2><<<gEmb, blk, CP_SMEM>>>(hb, w232, b2, x2, out, MTOT, EMB, MLPH);
}

// round 15
// speedup vs baseline: 1.4400x; 1.3195x over previous
#include <cuda_runtime.h>
#include <cuda_fp16.h>
#include <cstdint>

// ---------------------------------------------------------------------------
// Problem constants
// ---------------------------------------------------------------------------
#define BATCH 2
#define SEQ   2048
#define EMB   1024
#define HEADS 16
#define HDIM  64
#define MLPH  4096
#define MTOT  (BATCH * SEQ)   // 4096 rows

// ---------------------------------------------------------------------------
// Scratch (device globals: allocation-free)
// GEMM-A activations and all weights stored as fp16.
// ---------------------------------------------------------------------------
__device__ __half g_xn [MTOT * EMB];     // LN1 out
__device__ float  g_q  [MTOT * EMB];
__device__ float  g_k  [MTOT * EMB];
__device__ float  g_v  [MTOT * EMB];
__device__ __half g_att[MTOT * EMB];     // attn out
__device__ float  g_x2 [MTOT * EMB];
__device__ __half g_xn2[MTOT * EMB];     // LN2 out
__device__ __half g_h  [MTOT * MLPH];    // ReLU out
__device__ __half g_wq16[EMB * EMB];
__device__ __half g_wk16[EMB * EMB];
__device__ __half g_wv16[EMB * EMB];
__device__ __half g_wo16[EMB * EMB];
__device__ __half g_w116[EMB * MLPH];
__device__ __half g_w216[MLPH * EMB];

// ---------------------------------------------------------------------------
// Helpers
// ---------------------------------------------------------------------------
__device__ __forceinline__ uint32_t f2tf(float f) {
    uint32_t u;
    asm("cvt.rna.tf32.f32 %0, %1;" : "=r"(u) : "f"(f));
    return u;
}
__device__ __forceinline__ float ex2(float x) {
    float r;
    asm("ex2.approx.f32 %0, %1;" : "=f"(r) : "f"(x));
    return r;
}
__device__ __forceinline__ void mma_tf32(
    float* c, uint32_t a0, uint32_t a1, uint32_t a2, uint32_t a3,
    uint32_t b0, uint32_t b1)
{
    asm volatile(
        "mma.sync.aligned.m16n8k8.row.col.f32.tf32.tf32.f32 "
        "{%0,%1,%2,%3}, {%4,%5,%6,%7}, {%8,%9}, {%0,%1,%2,%3};"
        : "+f"(c[0]), "+f"(c[1]), "+f"(c[2]), "+f"(c[3])
        : "r"(a0), "r"(a1), "r"(a2), "r"(a3), "r"(b0), "r"(b1));
}
__device__ __forceinline__ void mma_f16(
    float* c, uint32_t a0, uint32_t a1, uint32_t a2, uint32_t a3,
    uint32_t b0, uint32_t b1)
{
    asm volatile(
        "mma.sync.aligned.m16n8k16.row.col.f32.f16.f16.f32 "
        "{%0,%1,%2,%3}, {%4,%5,%6,%7}, {%8,%9}, {%0,%1,%2,%3};"
        : "+f"(c[0]), "+f"(c[1]), "+f"(c[2]), "+f"(c[3])
        : "r"(a0), "r"(a1), "r"(a2), "r"(a3), "r"(b0), "r"(b1));
}
__device__ __forceinline__ void ldm_x4(uint32_t* r, uint32_t addr) {
    asm volatile("ldmatrix.sync.aligned.m8n8.x4.shared.b16 {%0,%1,%2,%3}, [%4];"
                 : "=r"(r[0]), "=r"(r[1]), "=r"(r[2]), "=r"(r[3]) : "r"(addr));
}
__device__ __forceinline__ void ldm_x2t(uint32_t& r0, uint32_t& r1, uint32_t addr) {
    asm volatile("ldmatrix.sync.aligned.m8n8.x2.trans.shared.b16 {%0,%1}, [%2];"
                 : "=r"(r0), "=r"(r1) : "r"(addr));
}
__device__ __forceinline__ uint32_t smem_u32(const void* p) {
    uint32_t a;
    asm("{ .reg .u64 t; cvta.to.shared.u64 t, %1; cvt.u32.u64 %0, t; }"
        : "=r"(a) : "l"(p));
    return a;
}
__device__ __forceinline__ void cpa16(uint32_t dst, const void* src) {
    asm volatile("cp.async.cg.shared.global [%0], [%1], 16;"
                 :: "r"(dst), "l"(src) : "memory");
}
#define CP_COMMIT() asm volatile("cp.async.commit_group;" ::: "memory")
#define CP_WAIT2()  asm volatile("cp.async.wait_group 2;" ::: "memory")

// ---------------------------------------------------------------------------
// LayerNorm: one block per row of 1024, 256 threads; output = fp16
// ---------------------------------------------------------------------------
__global__ __launch_bounds__(256) void ln_kernel(
    const float* __restrict__ x, const float* __restrict__ g,
    const float* __restrict__ b, __half* __restrict__ y)
{
    int row = blockIdx.x;
    int tid = threadIdx.x;
    const float4 v = ((const float4*)(x + (size_t)row * EMB))[tid];

    float s  = v.x + v.y + v.z + v.w;
    float ss = v.x * v.x + v.y * v.y + v.z * v.z + v.w * v.w;
    #pragma unroll
    for (int o = 16; o; o >>= 1) {
        s  += __shfl_xor_sync(0xffffffffu, s,  o);
        ss += __shfl_xor_sync(0xffffffffu, ss, o);
    }
    __shared__ float rs[8], rss[8];
    int w = tid >> 5, lane = tid & 31;
    if (lane == 0) { rs[w] = s; rss[w] = ss; }
    __syncthreads();
    s = 0.f; ss = 0.f;
    #pragma unroll
    for (int i = 0; i < 8; i++) { s += rs[i]; ss += rss[i]; }

    const float mean = s * (1.0f / EMB);
    const float var  = ss * (1.0f / EMB) - mean * mean;
    const float rstd = rsqrtf(var + 1e-5f);

    const float4 gv = ((const float4*)g)[tid];
    const float4 bv = ((const float4*)b)[tid];
    __half2 h0 = __floats2half2_rn((v.x - mean) * rstd * gv.x + bv.x,
                                   (v.y - mean) * rstd * gv.y + bv.y);
    __half2 h1 = __floats2half2_rn((v.z - mean) * rstd * gv.z + bv.z,
                                   (v.w - mean) * rstd * gv.w + bv.w);
    uint2 o;
    o.x = *(uint32_t*)&h0; o.y = *(uint32_t*)&h1;
    ((uint2*)(y + (size_t)row * EMB))[tid] = o;
}

// ---------------------------------------------------------------------------
// Weight convert fp32 -> fp16 (layout preserved [K][N])
// ---------------------------------------------------------------------------
__global__ __launch_bounds__(256) void wconv_kernel(
    const float* __restrict__ W, __half* __restrict__ Wt, int n4)
{
    int i = blockIdx.x * 256 + threadIdx.x;
    if (i < n4) {
        const float4 v = ((const float4*)W)[i];
        __half2 h0 = __floats2half2_rn(v.x, v.y);
        __half2 h1 = __floats2half2_rn(v.z, v.w);
        uint2 o;
        o.x = *(uint32_t*)&h0; o.y = *(uint32_t*)&h1;
        ((uint2*)Wt)[i] = o;
    }
}

// ---------------------------------------------------------------------------
// FP16 GEMM, cp.async 4-stage pipeline, ldmatrix fragments.
// C[M,N] = A[M,K] @ B[K,N] + bias (+relu->fp16 / +residual)
// CTA 128x256, BK=16, 256 threads (8 warps), warp tile 64x64 (m16n8k16).
// smem stage: A [128 rows][48B: 16 halves + pad], B [16 rows][528B].
// ldmatrix phases bank-conflict-free by row-stride construction.
// EPI: 0 = bias -> fp32, 1 = bias+relu -> fp16, 2 = bias+residual -> fp32
// ---------------------------------------------------------------------------
#define BM 128
#define BN 256
#define BK 16
#define A_ROWB 48                      // bytes per A row in smem
#define B_ROWB 528                     // bytes per B row in smem
#define ASTGB (BM * A_ROWB)            // 6144 B
#define BSTGB (BK * B_ROWB)            // 8448 B
#define STGB  (ASTGB + BSTGB)          // 14592 B
#define STAGES 4
#define CP_SMEM (STAGES * STGB)        // 58368 B

template<int EPI>
__device__ __forceinline__ void hgemm_body(
    const __half* __restrict__ A, const __half* __restrict__ B,
    const float* __restrict__ bias, const float* __restrict__ R,
    float* __restrict__ C, int M, int N, int K, int m0, int n0)
{
    extern __shared__ uint8_t smb[];
    const uint32_t sbase = smem_u32(smb);
    const int tid  = threadIdx.x;
    const int warp = tid >> 5;
    const int lane = tid & 31;
    const int gr   = lane >> 2;
    const int gc   = lane & 3;
    const int wm   = (warp & 1) * 64;
    const int wn   = (warp >> 1) * 64;

    // A loader: 256 chunks of 16B (128 rows x 2), 1/thread
    const int arow = tid >> 1, ah = (tid & 1) * 8;
    const uint32_t dA = (uint32_t)arow * A_ROWB + (tid & 1) * 16;
    // B loader: 512 chunks (16 rows x 32), 2/thread
    const int brow0 = tid >> 5,           bh0 = (tid & 31) * 8;
    const int brow1 = (tid + 256) >> 5,   bh1 = ((tid + 256) & 31) * 8;
    const uint32_t dB0 = ASTGB + (uint32_t)brow0 * B_ROWB + (tid & 31) * 16;
    const uint32_t dB1 = ASTGB + (uint32_t)brow1 * B_ROWB + ((tid + 256) & 31) * 16;

    const __half* Ab = A + (size_t)m0 * K;
    const __half* Bb = B + n0;

    const int nkt = K / BK;

    #pragma unroll
    for (int s = 0; s < STAGES - 1; s++) {
        if (s < nkt) {
            const uint32_t sb = sbase + s * STGB;
            const int k0 = s * BK;
            cpa16(sb + dA,  Ab + (size_t)arow * K + k0 + ah);
            cpa16(sb + dB0, Bb + (size_t)(k0 + brow0) * N + bh0);
            cpa16(sb + dB1, Bb + (size_t)(k0 + brow1) * N + bh1);
        }
        CP_COMMIT();
    }

    // fragment base addresses (within a stage)
    const uint32_t aAddr = sbase + (uint32_t)(wm + (lane & 15)) * A_ROWB
                                 + (lane >> 4) * 16;
    const uint32_t bAddr = sbase + ASTGB + (uint32_t)(lane & 15) * B_ROWB
                                 + (uint32_t)wn * 2;

    float acc[4][8][4];
    #pragma unroll
    for (int mt = 0; mt < 4; mt++)
        #pragma unroll
        for (int nt = 0; nt < 8; nt++)
            #pragma unroll
            for (int r = 0; r < 4; r++) acc[mt][nt][r] = 0.f;

    for (int kt = 0; kt < nkt; kt++) {
        CP_WAIT2();
        __syncthreads();

        if (kt + STAGES - 1 < nkt) {
            const uint32_t sb = sbase + ((kt + STAGES - 1) % STAGES) * STGB;
            const int k0 = (kt + STAGES - 1) * BK;
            cpa16(sb + dA,  Ab + (size_t)arow * K + k0 + ah);
            cpa16(sb + dB0, Bb + (size_t)(k0 + brow0) * N + bh0);
            cpa16(sb + dB1, Bb + (size_t)(k0 + brow1) * N + bh1);
        }
        CP_COMMIT();

        const uint32_t so = (kt % STAGES) * STGB;
        uint32_t af[4][4];
        #pragma unroll
        for (int mt = 0; mt < 4; mt++)
            ldm_x4(af[mt], aAddr + so + mt * 16 * A_ROWB);
        #pragma unroll
        for (int nt = 0; nt < 8; nt++) {
            uint32_t b0, b1;
            ldm_x2t(b0, b1, bAddr + so + nt * 16);
            #pragma unroll
            for (int mt = 0; mt < 4; mt++)
                mma_f16(acc[mt][nt], af[mt][0], af[mt][1], af[mt][2], af[mt][3],
                        b0, b1);
        }
    }

    // epilogue
    float2 bv[8];
    #pragma unroll
    for (int nt = 0; nt < 8; nt++)
        bv[nt] = *(const float2*)(bias + n0 + wn + nt * 8 + gc * 2);

    #pragma unroll
    for (int mt = 0; mt < 4; mt++) {
        const int gm = m0 + wm + mt * 16 + gr;
        #pragma unroll
        for (int nt = 0; nt < 8; nt++) {
            const int gn = n0 + wn + nt * 8 + gc * 2;
            float2 o0, o1;
            o0.x = acc[mt][nt][0] + bv[nt].x;
            o0.y = acc[mt][nt][1] + bv[nt].y;
            o1.x = acc[mt][nt][2] + bv[nt].x;
            o1.y = acc[mt][nt][3] + bv[nt].y;
            if (EPI == 1) {
                o0.x = fmaxf(o0.x, 0.f); o0.y = fmaxf(o0.y, 0.f);
                o1.x = fmaxf(o1.x, 0.f); o1.y = fmaxf(o1.y, 0.f);
                __half2 h0 = __floats2half2_rn(o0.x, o0.y);
                __half2 h1 = __floats2half2_rn(o1.x, o1.y);
                __half* Ch = (__half*)C;
                *(uint32_t*)(Ch + (size_t)gm * N + gn)       = *(uint32_t*)&h0;
                *(uint32_t*)(Ch + (size_t)(gm + 8) * N + gn) = *(uint32_t*)&h1;
            } else {
                if (EPI == 2) {
                    const float2 r0 = *(const float2*)(R + (size_t)gm * N + gn);
                    const float2 r1 = *(const float2*)(R + (size_t)(gm + 8) * N + gn);
                    o0.x += r0.x; o0.y += r0.y;
                    o1.x += r1.x; o1.y += r1.y;
                }
                *(float2*)(C + (size_t)gm * N + gn)       = o0;
                *(float2*)(C + (size_t)(gm + 8) * N + gn) = o1;
            }
        }
    }
}

template<int EPI>
__global__ __launch_bounds__(256, 1) void hgemm_kernel(
    const __half* __restrict__ A, const __half* __restrict__ B,
    const float* __restrict__ bias, const float* __restrict__ R,
    float* __restrict__ C, int M, int N, int K)
{
    hgemm_body<EPI>(A, B, bias, R, C, M, N, K,
                    blockIdx.y * BM, blockIdx.x * BN);
}

__global__ __launch_bounds__(256, 1) void qkvh_kernel(
    const __half* __restrict__ A,
    const __half* __restrict__ B0, const __half* __restrict__ B1,
    const __half* __restrict__ B2,
    const float* __restrict__ b0, const float* __restrict__ b1,
    const float* __restrict__ b2,
    float* __restrict__ C0, float* __restrict__ C1, float* __restrict__ C2)
{
    const __half* B = (blockIdx.z == 0) ? B0 : (blockIdx.z == 1) ? B1 : B2;
    const float* bb = (blockIdx.z == 0) ? b0 : (blockIdx.z == 1) ? b1 : b2;
    float* C = (blockIdx.z == 0) ? C0 : (blockIdx.z == 1) ? C1 : C2;
    hgemm_body<0>(A, B, bb, nullptr, C, MTOT, EMB, EMB,
                  blockIdx.y * BM, blockIdx.x * BN);
}

// ---------------------------------------------------------------------------
// Flash-attention v3: tf32 tensor cores + log2-domain online softmax.
// Output packed to fp16 (consumed by Wo GEMM as A).
// ---------------------------------------------------------------------------
#define AQT 128
#define AKT 64
#define QP 68
#define KP 72
#define ATT_SMEM ((128*QP + 64*KP + 64*KP + 128*QP) * 4)   // 106496 B
#define QSCALE 0.18033688011112042f   // 0.125 * log2(e)

__global__ __launch_bounds__(256, 1) void attn3_kernel(
    const float* __restrict__ Q, const float* __restrict__ Km,
    const float* __restrict__ Vm, __half* __restrict__ O)
{
    extern __shared__ uint32_t smu[];
    uint32_t* sQ = smu;
    uint32_t* sK = sQ + 128 * QP;
    uint32_t* sV = sK + 64 * KP;
    uint32_t* sP = sV + 64 * KP;

    const int bh = blockIdx.y;
    const int b  = bh / HEADS;
    const int h  = bh % HEADS;
    const int q0 = blockIdx.x * AQT;
    const int tid  = threadIdx.x;
    const int warp = tid >> 5;
    const int lane = tid & 31;
    const int gr   = lane >> 2;
    const int gc   = lane & 3;
    const int wq0  = warp * 16;
    uint32_t* sPw = sP + warp * 16 * QP;

    const size_t base = ((size_t)b * SEQ) * EMB + (size_t)h * HDIM;
    const float* Qb = Q  + base;
    const float* Kb = Km + base;
    const float* Vb = Vm + base;

    #pragma unroll
    for (int t = 0; t < 8; t++) {
        int idx = tid + t * 256;
        int qr = idx >> 4, c4 = (idx & 15) * 4;
        float4 v = *(const float4*)(Qb + (size_t)(q0 + qr) * EMB + c4);
        sQ[qr * QP + c4 + 0] = f2tf(v.x * QSCALE);
        sQ[qr * QP + c4 + 1] = f2tf(v.y * QSCALE);
        sQ[qr * QP + c4 + 2] = f2tf(v.z * QSCALE);
        sQ[qr * QP + c4 + 3] = f2tf(v.w * QSCALE);
    }

    float m0 = -1e30f, m1 = -1e30f, l0 = 0.f, l1 = 0.f;
    float oacc[8][4];
    #pragma unroll
    for (int nt = 0; nt < 8; nt++)
        #pragma unroll
        for (int r = 0; r < 4; r++) oacc[nt][r] = 0.f;

    const int kr0 = tid >> 4;
    const int kc4 = (tid & 15) * 4;
    float4 pk[4], pv[4];
    #pragma unroll
    for (int t = 0; t < 4; t++) {
        size_t goff = (size_t)(kr0 + t * 16) * EMB + kc4;
        pk[t] = *(const float4*)(Kb + goff);
        pv[t] = *(const float4*)(Vb + goff);
    }

    for (int kt = 0; kt < SEQ / AKT; kt++) {
        #pragma unroll
        for (int t = 0; t < 4; t++) {
            int kr = kr0 + t * 16;
            sK[(kc4 + 0) * KP + kr] = f2tf(pk[t].x);
            sK[(kc4 + 1) * KP + kr] = f2tf(pk[t].y);
            sK[(kc4 + 2) * KP + kr] = f2tf(pk[t].z);
            sK[(kc4 + 3) * KP + kr] = f2tf(pk[t].w);
            uint4 u;
            u.x = f2tf(pv[t].x); u.y = f2tf(pv[t].y);
            u.z = f2tf(pv[t].z); u.w = f2tf(pv[t].w);
            *(uint4*)&sV[kr * KP + kc4] = u;
        }
        __syncthreads();

        if (kt + 1 < SEQ / AKT) {
            const size_t tb = (size_t)(kt + 1) * AKT * EMB;
            #pragma unroll
            for (int t = 0; t < 4; t++) {
                size_t goff = tb + (size_t)(kr0 + t * 16) * EMB + kc4;
                pk[t] = *(const float4*)(Kb + goff);
                pv[t] = *(const float4*)(Vb + goff);
            }
        }

        float sacc[8][4];
        #pragma unroll
        for (int nt = 0; nt < 8; nt++)
            #pragma unroll
            for (int r = 0; r < 4; r++) sacc[nt][r] = 0.f;

        #pragma unroll
        for (int ks = 0; ks < 8; ks++) {
            const int ka = ks * 8 + gc;
            const uint32_t a0 = sQ[(wq0 + gr) * QP + ka];
            const uint32_t a1 = sQ[(wq0 + gr + 8) * QP + ka];
            const uint32_t a2 = sQ[(wq0 + gr) * QP + ka + 4];
            const uint32_t a3 = sQ[(wq0 + gr + 8) * QP + ka + 4];
            #pragma unroll
            for (int nt = 0; nt < 8; nt++) {
                const uint32_t b0 = sK[ka * KP + nt * 8 + gr];
                const uint32_t b1 = sK[(ka + 4) * KP + nt * 8 + gr];
                mma_tf32(sacc[nt], a0, a1, a2, a3, b0, b1);
            }
        }

        float t0 = -1e30f, t1 = -1e30f;
        #pragma unroll
        for (int nt = 0; nt < 8; nt++) {
            t0 = fmaxf(t0, fmaxf(sacc[nt][0], sacc[nt][1]));
            t1 = fmaxf(t1, fmaxf(sacc[nt][2], sacc[nt][3]));
        }
        t0 = fmaxf(t0, __shfl_xor_sync(0xffffffffu, t0, 1));
        t0 = fmaxf(t0, __shfl_xor_sync(0xffffffffu, t0, 2));
        t1 = fmaxf(t1, __shfl_xor_sync(0xffffffffu, t1, 1));
        t1 = fmaxf(t1, __shfl_xor_sync(0xffffffffu, t1, 2));
        const float nm0 = fmaxf(m0, t0);
        const float nm1 = fmaxf(m1, t1);
        const float c0 = ex2(m0 - nm0);
        const float c1 = ex2(m1 - nm1);
        float ps0 = 0.f, ps1 = 0.f;
        #pragma unroll
        for (int nt = 0; nt < 8; nt++) {
            const float p00 = ex2(sacc[nt][0] - nm0);
            const float p01 = ex2(sacc[nt][1] - nm0);
            const float p10 = ex2(sacc[nt][2] - nm1);
            const float p11 = ex2(sacc[nt][3] - nm1);
            ps0 += p00 + p01;
            ps1 += p10 + p11;
            sPw[gr * QP + nt * 8 + gc * 2]           = f2tf(p00);
            sPw[gr * QP + nt * 8 + gc * 2 + 1]       = f2tf(p01);
            sPw[(gr + 8) * QP + nt * 8 + gc * 2]     = f2tf(p10);
            sPw[(gr + 8) * QP + nt * 8 + gc * 2 + 1] = f2tf(p11);
        }
        ps0 += __shfl_xor_sync(0xffffffffu, ps0, 1);
        ps0 += __shfl_xor_sync(0xffffffffu, ps0, 2);
        ps1 += __shfl_xor_sync(0xffffffffu, ps1, 1);
        ps1 += __shfl_xor_sync(0xffffffffu, ps1, 2);
        l0 = l0 * c0 + ps0;
        l1 = l1 * c1 + ps1;
        m0 = nm0; m1 = nm1;
        #pragma unroll
        for (int nt = 0; nt < 8; nt++) {
            oacc[nt][0] *= c0; oacc[nt][1] *= c0;
            oacc[nt][2] *= c1; oacc[nt][3] *= c1;
        }
        __syncwarp();

        #pragma unroll
        for (int ks = 0; ks < 8; ks++) {
            const int kk = ks * 8 + gc;
            const uint32_t a0 = sPw[gr * QP + kk];
            const uint32_t a1 = sPw[(gr + 8) * QP + kk];
            const uint32_t a2 = sPw[gr * QP + kk + 4];
            const uint32_t a3 = sPw[(gr + 8) * QP + kk + 4];
            #pragma unroll
            for (int nt = 0; nt < 8; nt++) {
                const uint32_t b0 = sV[kk * KP + nt * 8 + gr];
                const uint32_t b1 = sV[(kk + 4) * KP + nt * 8 + gr];
                mma_tf32(oacc[nt], a0, a1, a2, a3, b0, b1);
            }
        }
        __syncthreads();
    }

    const float inv0 = 1.0f / l0;
    const float inv1 = 1.0f / l1;
    __half* O0 = O + base + (size_t)(q0 + wq0 + gr) * EMB;
    __half* O1 = O + base + (size_t)(q0 + wq0 + gr + 8) * EMB;
    #pragma unroll
    for (int nt = 0; nt < 8; nt++) {
        const int cn = nt * 8 + gc * 2;
        __half2 h0 = __floats2half2_rn(oacc[nt][0] * inv0, oacc[nt][1] * inv0);
        __half2 h1 = __floats2half2_rn(oacc[nt][2] * inv1, oacc[nt][3] * inv1);
        *(uint32_t*)(O0 + cn) = *(uint32_t*)&h0;
        *(uint32_t*)(O1 + cn) = *(uint32_t*)&h1;
    }
}

// ---------------------------------------------------------------------------
// Launch
// ---------------------------------------------------------------------------
extern "C" void kernel_launch(void* const* d_in, const int* in_sizes, int n_in,
                              void* d_out, int out_size)
{
    const float* x    = (const float*)d_in[0];
    const float* ln1g = (const float*)d_in[1];
    const float* ln1b = (const float*)d_in[2];
    const float* ln2g = (const float*)d_in[3];
    const float* ln2b = (const float*)d_in[4];
    const float* Wq   = (const float*)d_in[5];
    const float* bq   = (const float*)d_in[6];
    const float* Wk   = (const float*)d_in[7];
    const float* bk   = (const float*)d_in[8];
    const float* Wv   = (const float*)d_in[9];
    const float* bv   = (const float*)d_in[10];
    const float* Wo   = (const float*)d_in[11];
    const float* bo   = (const float*)d_in[12];
    const float* W1   = (const float*)d_in[13];
    const float* b1   = (const float*)d_in[14];
    const float* W2   = (const float*)d_in[15];
    const float* b2   = (const float*)d_in[16];
    float* out = (float*)d_out;

    __half *xn, *att, *xn2, *hb;
    float *q, *k, *v, *x2;
    __half *wq16, *wk16, *wv16, *wo16, *w116, *w216;
    cudaGetSymbolAddress((void**)&xn,  g_xn);
    cudaGetSymbolAddress((void**)&q,   g_q);
    cudaGetSymbolAddress((void**)&k,   g_k);
    cudaGetSymbolAddress((void**)&v,   g_v);
    cudaGetSymbolAddress((void**)&att, g_att);
    cudaGetSymbolAddress((void**)&x2,  g_x2);
    cudaGetSymbolAddress((void**)&xn2, g_xn2);
    cudaGetSymbolAddress((void**)&hb,  g_h);
    cudaGetSymbolAddress((void**)&wq16, g_wq16);
    cudaGetSymbolAddress((void**)&wk16, g_wk16);
    cudaGetSymbolAddress((void**)&wv16, g_wv16);
    cudaGetSymbolAddress((void**)&wo16, g_wo16);
    cudaGetSymbolAddress((void**)&w116, g_w116);
    cudaGetSymbolAddress((void**)&w216, g_w216);

    cudaFuncSetAttribute(attn3_kernel,
                         cudaFuncAttributeMaxDynamicSharedMemorySize, ATT_SMEM);
    cudaFuncSetAttribute(hgemm_kernel<1>,
                         cudaFuncAttributeMaxDynamicSharedMemorySize, CP_SMEM);
    cudaFuncSetAttribute(hgemm_kernel<2>,
                         cudaFuncAttributeMaxDynamicSharedMemorySize, CP_SMEM);
    cudaFuncSetAttribute(qkvh_kernel,
                         cudaFuncAttributeMaxDynamicSharedMemorySize, CP_SMEM);

    const dim3 blk(256);
    const dim3 gEmb(EMB / BN, MTOT / BM);        // (4, 32)
    const dim3 gMlp(MLPH / BN, MTOT / BM);       // (16, 32)
    const dim3 gQKV(EMB / BN, MTOT / BM, 3);
    const dim3 gAtt(SEQ / AQT, BATCH * HEADS);

    // 0. Weight convert fp32 -> fp16
    const int c1m = EMB * EMB / 4, c4m = EMB * MLPH / 4;
    wconv_kernel<<<(c1m + 255) / 256, blk>>>(Wq, wq16, c1m);
    wconv_kernel<<<(c1m + 255) / 256, blk>>>(Wk, wk16, c1m);
    wconv_kernel<<<(c1m + 255) / 256, blk>>>(Wv, wv16, c1m);
    wconv_kernel<<<(c1m + 255) / 256, blk>>>(Wo, wo16, c1m);
    wconv_kernel<<<(c4m + 255) / 256, blk>>>(W1, w116, c4m);
    wconv_kernel<<<(c4m + 255) / 256, blk>>>(W2, w216, c4m);

    // 1. LN1 (-> fp16)
    ln_kernel<<<MTOT, blk>>>(x, ln1g, ln1b, xn);
    // 2. QKV projections (fp16 tensor cores)
    qkvh_kernel<<<gQKV, blk, CP_SMEM>>>(xn, wq16, wk16, wv16, bq, bk, bv, q, k, v);
    // 3. Attention (-> fp16)
    attn3_kernel<<<gAtt, blk, ATT_SMEM>>>(q, k, v, att);
    // 4. Output projection + residual
    hgemm_kernel<2><<<gEmb, blk, CP_SMEM>>>(att, wo16, bo, x, x2, MTOT, EMB, EMB);
    // 5. LN2 (-> fp16)
    ln_kernel<<<MTOT, blk>>>(x2, ln2g, ln2b, xn2);
    // 6. MLP up + ReLU (-> fp16)
    hgemm_kernel<1><<<gMlp, blk, CP_SMEM>>>(xn2, w116, b1, nullptr, (float*)hb,
                                            MTOT, MLPH, EMB);
    // 7. MLP down + residual -> output
    hgemm_kernel<2><<<gEmb, blk, CP_SMEM>>>(hb, w216, b2, x2, out, MTOT, EMB, MLPH);
}

// round 16
// speedup vs baseline: 1.8121x; 1.2584x over previous
#include <cuda_runtime.h>
#include <cuda_fp16.h>
#include <cstdint>

// ---------------------------------------------------------------------------
// Problem constants
// ---------------------------------------------------------------------------
#define BATCH 2
#define SEQ   2048
#define EMB   1024
#define HEADS 16
#define HDIM  64
#define MLPH  4096
#define MTOT  (BATCH * SEQ)   // 4096 rows

// ---------------------------------------------------------------------------
// Scratch (device globals: allocation-free)
// ---------------------------------------------------------------------------
__device__ __half g_xn [MTOT * EMB];     // LN1 out
__device__ float  g_q  [MTOT * EMB];
__device__ float  g_k  [MTOT * EMB];
__device__ float  g_v  [MTOT * EMB];
__device__ __half g_att[MTOT * EMB];     // attn out
__device__ float  g_x2 [MTOT * EMB];
__device__ __half g_xn2[MTOT * EMB];     // LN2 out
__device__ __half g_h  [MTOT * MLPH];    // ReLU out
__device__ __half g_wq16[EMB * EMB];
__device__ __half g_wk16[EMB * EMB];
__device__ __half g_wv16[EMB * EMB];
__device__ __half g_wo16[EMB * EMB];
__device__ __half g_w116[EMB * MLPH];
__device__ __half g_w216[MLPH * EMB];

// ---------------------------------------------------------------------------
// Helpers
// ---------------------------------------------------------------------------
__device__ __forceinline__ float ex2(float x) {
    float r;
    asm("ex2.approx.f32 %0, %1;" : "=f"(r) : "f"(x));
    return r;
}
__device__ __forceinline__ void mma_f16(
    float* c, uint32_t a0, uint32_t a1, uint32_t a2, uint32_t a3,
    uint32_t b0, uint32_t b1)
{
    asm volatile(
        "mma.sync.aligned.m16n8k16.row.col.f32.f16.f16.f32 "
        "{%0,%1,%2,%3}, {%4,%5,%6,%7}, {%8,%9}, {%0,%1,%2,%3};"
        : "+f"(c[0]), "+f"(c[1]), "+f"(c[2]), "+f"(c[3])
        : "r"(a0), "r"(a1), "r"(a2), "r"(a3), "r"(b0), "r"(b1));
}
__device__ __forceinline__ void ldm_x4(uint32_t* r, uint32_t addr) {
    asm volatile("ldmatrix.sync.aligned.m8n8.x4.shared.b16 {%0,%1,%2,%3}, [%4];"
                 : "=r"(r[0]), "=r"(r[1]), "=r"(r[2]), "=r"(r[3]) : "r"(addr));
}
__device__ __forceinline__ void ldm_x2t(uint32_t& r0, uint32_t& r1, uint32_t addr) {
    asm volatile("ldmatrix.sync.aligned.m8n8.x2.trans.shared.b16 {%0,%1}, [%2];"
                 : "=r"(r0), "=r"(r1) : "r"(addr));
}
__device__ __forceinline__ uint32_t smem_u32(const void* p) {
    uint32_t a;
    asm("{ .reg .u64 t; cvta.to.shared.u64 t, %1; cvt.u32.u64 %0, t; }"
        : "=r"(a) : "l"(p));
    return a;
}
__device__ __forceinline__ void cpa16(uint32_t dst, const void* src) {
    asm volatile("cp.async.cg.shared.global [%0], [%1], 16;"
                 :: "r"(dst), "l"(src) : "memory");
}
#define CP_COMMIT() asm volatile("cp.async.commit_group;" ::: "memory")
#define CP_WAIT2()  asm volatile("cp.async.wait_group 2;" ::: "memory")

// ---------------------------------------------------------------------------
// LayerNorm: one block per row of 1024, 256 threads; output = fp16
// ---------------------------------------------------------------------------
__global__ __launch_bounds__(256) void ln_kernel(
    const float* __restrict__ x, const float* __restrict__ g,
    const float* __restrict__ b, __half* __restrict__ y)
{
    int row = blockIdx.x;
    int tid = threadIdx.x;
    const float4 v = ((const float4*)(x + (size_t)row * EMB))[tid];

    float s  = v.x + v.y + v.z + v.w;
    float ss = v.x * v.x + v.y * v.y + v.z * v.z + v.w * v.w;
    #pragma unroll
    for (int o = 16; o; o >>= 1) {
        s  += __shfl_xor_sync(0xffffffffu, s,  o);
        ss += __shfl_xor_sync(0xffffffffu, ss, o);
    }
    __shared__ float rs[8], rss[8];
    int w = tid >> 5, lane = tid & 31;
    if (lane == 0) { rs[w] = s; rss[w] = ss; }
    __syncthreads();
    s = 0.f; ss = 0.f;
    #pragma unroll
    for (int i = 0; i < 8; i++) { s += rs[i]; ss += rss[i]; }

    const float mean = s * (1.0f / EMB);
    const float var  = ss * (1.0f / EMB) - mean * mean;
    const float rstd = rsqrtf(var + 1e-5f);

    const float4 gv = ((const float4*)g)[tid];
    const float4 bv = ((const float4*)b)[tid];
    __half2 h0 = __floats2half2_rn((v.x - mean) * rstd * gv.x + bv.x,
                                   (v.y - mean) * rstd * gv.y + bv.y);
    __half2 h1 = __floats2half2_rn((v.z - mean) * rstd * gv.z + bv.z,
                                   (v.w - mean) * rstd * gv.w + bv.w);
    uint2 o;
    o.x = *(uint32_t*)&h0; o.y = *(uint32_t*)&h1;
    ((uint2*)(y + (size_t)row * EMB))[tid] = o;
}

// ---------------------------------------------------------------------------
// Weight convert fp32 -> fp16 (layout preserved [K][N])
// ---------------------------------------------------------------------------
__global__ __launch_bounds__(256) void wconv_kernel(
    const float* __restrict__ W, __half* __restrict__ Wt, int n4)
{
    int i = blockIdx.x * 256 + threadIdx.x;
    if (i < n4) {
        const float4 v = ((const float4*)W)[i];
        __half2 h0 = __floats2half2_rn(v.x, v.y);
        __half2 h1 = __floats2half2_rn(v.z, v.w);
        uint2 o;
        o.x = *(uint32_t*)&h0; o.y = *(uint32_t*)&h1;
        ((uint2*)Wt)[i] = o;
    }
}

// ---------------------------------------------------------------------------
// FP16 GEMM, cp.async 4-stage pipeline, ldmatrix fragments. (proven R15)
// ---------------------------------------------------------------------------
#define BM 128
#define BN 256
#define BK 16
#define A_ROWB 48
#define B_ROWB 528
#define ASTGB (BM * A_ROWB)            // 6144 B
#define BSTGB (BK * B_ROWB)            // 8448 B
#define STGB  (ASTGB + BSTGB)          // 14592 B
#define STAGES 4
#define CP_SMEM (STAGES * STGB)        // 58368 B

template<int EPI>
__device__ __forceinline__ void hgemm_body(
    const __half* __restrict__ A, const __half* __restrict__ B,
    const float* __restrict__ bias, const float* __restrict__ R,
    float* __restrict__ C, int M, int N, int K, int m0, int n0)
{
    extern __shared__ uint8_t smb[];
    const uint32_t sbase = smem_u32(smb);
    const int tid  = threadIdx.x;
    const int warp = tid >> 5;
    const int lane = tid & 31;
    const int gr   = lane >> 2;
    const int gc   = lane & 3;
    const int wm   = (warp & 1) * 64;
    const int wn   = (warp >> 1) * 64;

    const int arow = tid >> 1, ah = (tid & 1) * 8;
    const uint32_t dA = (uint32_t)arow * A_ROWB + (tid & 1) * 16;
    const int brow0 = tid >> 5,           bh0 = (tid & 31) * 8;
    const int brow1 = (tid + 256) >> 5,   bh1 = ((tid + 256) & 31) * 8;
    const uint32_t dB0 = ASTGB + (uint32_t)brow0 * B_ROWB + (tid & 31) * 16;
    const uint32_t dB1 = ASTGB + (uint32_t)brow1 * B_ROWB + ((tid + 256) & 31) * 16;

    const __half* Ab = A + (size_t)m0 * K;
    const __half* Bb = B + n0;

    const int nkt = K / BK;

    #pragma unroll
    for (int s = 0; s < STAGES - 1; s++) {
        if (s < nkt) {
            const uint32_t sb = sbase + s * STGB;
            const int k0 = s * BK;
            cpa16(sb + dA,  Ab + (size_t)arow * K + k0 + ah);
            cpa16(sb + dB0, Bb + (size_t)(k0 + brow0) * N + bh0);
            cpa16(sb + dB1, Bb + (size_t)(k0 + brow1) * N + bh1);
        }
        CP_COMMIT();
    }

    const uint32_t aAddr = sbase + (uint32_t)(wm + (lane & 15)) * A_ROWB
                                 + (lane >> 4) * 16;
    const uint32_t bAddr = sbase + ASTGB + (uint32_t)(lane & 15) * B_ROWB
                                 + (uint32_t)wn * 2;

    float acc[4][8][4];
    #pragma unroll
    for (int mt = 0; mt < 4; mt++)
        #pragma unroll
        for (int nt = 0; nt < 8; nt++)
            #pragma unroll
            for (int r = 0; r < 4; r++) acc[mt][nt][r] = 0.f;

    for (int kt = 0; kt < nkt; kt++) {
        CP_WAIT2();
        __syncthreads();

        if (kt + STAGES - 1 < nkt) {
            const uint32_t sb = sbase + ((kt + STAGES - 1) % STAGES) * STGB;
            const int k0 = (kt + STAGES - 1) * BK;
            cpa16(sb + dA,  Ab + (size_t)arow * K + k0 + ah);
            cpa16(sb + dB0, Bb + (size_t)(k0 + brow0) * N + bh0);
            cpa16(sb + dB1, Bb + (size_t)(k0 + brow1) * N + bh1);
        }
        CP_COMMIT();

        const uint32_t so = (kt % STAGES) * STGB;
        uint32_t af[4][4];
        #pragma unroll
        for (int mt = 0; mt < 4; mt++)
            ldm_x4(af[mt], aAddr + so + mt * 16 * A_ROWB);
        #pragma unroll
        for (int nt = 0; nt < 8; nt++) {
            uint32_t b0, b1;
            ldm_x2t(b0, b1, bAddr + so + nt * 16);
            #pragma unroll
            for (int mt = 0; mt < 4; mt++)
                mma_f16(acc[mt][nt], af[mt][0], af[mt][1], af[mt][2], af[mt][3],
                        b0, b1);
        }
    }

    float2 bv[8];
    #pragma unroll
    for (int nt = 0; nt < 8; nt++)
        bv[nt] = *(const float2*)(bias + n0 + wn + nt * 8 + gc * 2);

    #pragma unroll
    for (int mt = 0; mt < 4; mt++) {
        const int gm = m0 + wm + mt * 16 + gr;
        #pragma unroll
        for (int nt = 0; nt < 8; nt++) {
            const int gn = n0 + wn + nt * 8 + gc * 2;
            float2 o0, o1;
            o0.x = acc[mt][nt][0] + bv[nt].x;
            o0.y = acc[mt][nt][1] + bv[nt].y;
            o1.x = acc[mt][nt][2] + bv[nt].x;
            o1.y = acc[mt][nt][3] + bv[nt].y;
            if (EPI == 1) {
                o0.x = fmaxf(o0.x, 0.f); o0.y = fmaxf(o0.y, 0.f);
                o1.x = fmaxf(o1.x, 0.f); o1.y = fmaxf(o1.y, 0.f);
                __half2 h0 = __floats2half2_rn(o0.x, o0.y);
                __half2 h1 = __floats2half2_rn(o1.x, o1.y);
                __half* Ch = (__half*)C;
                *(uint32_t*)(Ch + (size_t)gm * N + gn)       = *(uint32_t*)&h0;
                *(uint32_t*)(Ch + (size_t)(gm + 8) * N + gn) = *(uint32_t*)&h1;
            } else {
                if (EPI == 2) {
                    const float2 r0 = *(const float2*)(R + (size_t)gm * N + gn);
                    const float2 r1 = *(const float2*)(R + (size_t)(gm + 8) * N + gn);
                    o0.x += r0.x; o0.y += r0.y;
                    o1.x += r1.x; o1.y += r1.y;
                }
                *(float2*)(C + (size_t)gm * N + gn)       = o0;
                *(float2*)(C + (size_t)(gm + 8) * N + gn) = o1;
            }
        }
    }
}

template<int EPI>
__global__ __launch_bounds__(256, 1) void hgemm_kernel(
    const __half* __restrict__ A, const __half* __restrict__ B,
    const float* __restrict__ bias, const float* __restrict__ R,
    float* __restrict__ C, int M, int N, int K)
{
    hgemm_body<EPI>(A, B, bias, R, C, M, N, K,
                    blockIdx.y * BM, blockIdx.x * BN);
}

__global__ __launch_bounds__(256, 1) void qkvh_kernel(
    const __half* __restrict__ A,
    const __half* __restrict__ B0, const __half* __restrict__ B1,
    const __half* __restrict__ B2,
    const float* __restrict__ b0, const float* __restrict__ b1,
    const float* __restrict__ b2,
    float* __restrict__ C0, float* __restrict__ C1, float* __restrict__ C2)
{
    const __half* B = (blockIdx.z == 0) ? B0 : (blockIdx.z == 1) ? B1 : B2;
    const float* bb = (blockIdx.z == 0) ? b0 : (blockIdx.z == 1) ? b1 : b2;
    float* C = (blockIdx.z == 0) ? C0 : (blockIdx.z == 1) ? C1 : C2;
    hgemm_body<0>(A, B, bb, nullptr, C, MTOT, EMB, EMB,
                  blockIdx.y * BM, blockIdx.x * BN);
}

// ---------------------------------------------------------------------------
// Flash-attention v4: fp16 tensor cores (m16n8k16 + ldmatrix),
// log2-domain online softmax. 128 q/CTA, 8 warps x 16 q-rows, 64-key tiles.
// smem (144 B row stride, conflict-free ldmatrix):
//   sQ [128 q][64 d]   fp16 row-major  (A, S-phase)
//   sK [64 d][64 key]  fp16 d-major    (B, S-phase via x2.trans)
//   sV [64 key][64 d]  fp16 key-major  (B, PV-phase via x2.trans)
//   sP 8 x [16 q][64 key] fp16         (A, PV-phase; per-warp)
// ---------------------------------------------------------------------------
#define AQT 128
#define AKT 64
#define RB 144                         // smem row stride in bytes
#define SQ_OFF 0
#define SK_OFF (128 * RB)              // 18432
#define SV_OFF (SK_OFF + 64 * RB)      // 27648
#define SP_OFF (SV_OFF + 64 * RB)      // 36864
#define ATT_SMEM (SP_OFF + 8 * 16 * RB)  // 55296 B
#define QSCALE 0.18033688011112042f    // 0.125 * log2(e)

__global__ __launch_bounds__(256, 1) void attn4_kernel(
    const float* __restrict__ Q, const float* __restrict__ Km,
    const float* __restrict__ Vm, __half* __restrict__ O)
{
    extern __shared__ uint8_t sma[];
    const uint32_t sbase = smem_u32(sma);

    const int bh = blockIdx.y;
    const int b  = bh / HEADS;
    const int h  = bh % HEADS;
    const int q0 = blockIdx.x * AQT;
    const int tid  = threadIdx.x;
    const int warp = tid >> 5;
    const int lane = tid & 31;
    const int gr   = lane >> 2;
    const int gc   = lane & 3;
    const int wq0  = warp * 16;
    uint8_t* sPw = sma + SP_OFF + warp * 16 * RB;

    const size_t base = ((size_t)b * SEQ) * EMB + (size_t)h * HDIM;
    const float* Qb = Q  + base;
    const float* Kb = Km + base;
    const float* Vb = Vm + base;

    // Q tile: 128 rows x 64 d, pre-scaled into log2 domain, fp16
    #pragma unroll
    for (int t = 0; t < 8; t++) {
        int idx = tid + t * 256;
        int qr = idx >> 4, c4 = (idx & 15) * 4;
        float4 v = *(const float4*)(Qb + (size_t)(q0 + qr) * EMB + c4);
        __half2 h0 = __floats2half2_rn(v.x * QSCALE, v.y * QSCALE);
        __half2 h1 = __floats2half2_rn(v.z * QSCALE, v.w * QSCALE);
        uint2 u; u.x = *(uint32_t*)&h0; u.y = *(uint32_t*)&h1;
        *(uint2*)(sma + SQ_OFF + qr * RB + c4 * 2) = u;
    }

    float m0 = -1e30f, m1 = -1e30f, l0 = 0.f, l1 = 0.f;
    float oacc[8][4];
    #pragma unroll
    for (int nt = 0; nt < 8; nt++)
        #pragma unroll
        for (int r = 0; r < 4; r++) oacc[nt][r] = 0.f;

    // K/V prefetch (64 rows x 64 d each)
    const int kr0 = tid >> 4;
    const int kc4 = (tid & 15) * 4;
    float4 pk[4], pv[4];
    #pragma unroll
    for (int t = 0; t < 4; t++) {
        size_t goff = (size_t)(kr0 + t * 16) * EMB + kc4;
        pk[t] = *(const float4*)(Kb + goff);
        pv[t] = *(const float4*)(Vb + goff);
    }

    // fragment base addresses
    const uint32_t aQ = sbase + SQ_OFF + (uint32_t)(wq0 + (lane & 15)) * RB
                              + (lane >> 4) * 16;
    const uint32_t bK = sbase + SK_OFF + (uint32_t)(lane & 15) * RB;
    const uint32_t bV = sbase + SV_OFF + (uint32_t)(lane & 15) * RB;
    const uint32_t aP = sbase + SP_OFF + (uint32_t)warp * 16 * RB
                              + (uint32_t)(lane & 15) * RB + (lane >> 4) * 16;

    for (int kt = 0; kt < SEQ / AKT; kt++) {
        // commit K (d-major, fp16 scalar) and V (key-major, fp16 vector)
        #pragma unroll
        for (int t = 0; t < 4; t++) {
            int kr = kr0 + t * 16;
            *(__half*)(sma + SK_OFF + (kc4 + 0) * RB + kr * 2) = __float2half(pk[t].x);
            *(__half*)(sma + SK_OFF + (kc4 + 1) * RB + kr * 2) = __float2half(pk[t].y);
            *(__half*)(sma + SK_OFF + (kc4 + 2) * RB + kr * 2) = __float2half(pk[t].z);
            *(__half*)(sma + SK_OFF + (kc4 + 3) * RB + kr * 2) = __float2half(pk[t].w);
            __half2 h0 = __floats2half2_rn(pv[t].x, pv[t].y);
            __half2 h1 = __floats2half2_rn(pv[t].z, pv[t].w);
            uint2 u; u.x = *(uint32_t*)&h0; u.y = *(uint32_t*)&h1;
            *(uint2*)(sma + SV_OFF + kr * RB + kc4 * 2) = u;
        }
        __syncthreads();

        if (kt + 1 < SEQ / AKT) {
            const size_t tb = (size_t)(kt + 1) * AKT * EMB;
            #pragma unroll
            for (int t = 0; t < 4; t++) {
                size_t goff = tb + (size_t)(kr0 + t * 16) * EMB + kc4;
                pk[t] = *(const float4*)(Kb + goff);
                pv[t] = *(const float4*)(Vb + goff);
            }
        }

        // ---- S = Q @ K^T  (log2-scaled): 4 ksteps x 8 nt
        float sacc[8][4];
        #pragma unroll
        for (int nt = 0; nt < 8; nt++)
            #pragma unroll
            for (int r = 0; r < 4; r++) sacc[nt][r] = 0.f;

        #pragma unroll
        for (int ks = 0; ks < 4; ks++) {
            uint32_t af[4];
            ldm_x4(af, aQ + ks * 32);
            #pragma unroll
            for (int nt = 0; nt < 8; nt++) {
                uint32_t b0, b1;
                ldm_x2t(b0, b1, bK + ks * 16 * RB + nt * 16);
                mma_f16(sacc[nt], af[0], af[1], af[2], af[3], b0, b1);
            }
        }

        // ---- online softmax (base-2)
        float t0 = -1e30f, t1 = -1e30f;
        #pragma unroll
        for (int nt = 0; nt < 8; nt++) {
            t0 = fmaxf(t0, fmaxf(sacc[nt][0], sacc[nt][1]));
            t1 = fmaxf(t1, fmaxf(sacc[nt][2], sacc[nt][3]));
        }
        t0 = fmaxf(t0, __shfl_xor_sync(0xffffffffu, t0, 1));
        t0 = fmaxf(t0, __shfl_xor_sync(0xffffffffu, t0, 2));
        t1 = fmaxf(t1, __shfl_xor_sync(0xffffffffu, t1, 1));
        t1 = fmaxf(t1, __shfl_xor_sync(0xffffffffu, t1, 2));
        const float nm0 = fmaxf(m0, t0);
        const float nm1 = fmaxf(m1, t1);
        const float c0 = ex2(m0 - nm0);
        const float c1 = ex2(m1 - nm1);
        float ps0 = 0.f, ps1 = 0.f;
        #pragma unroll
        for (int nt = 0; nt < 8; nt++) {
            const float p00 = ex2(sacc[nt][0] - nm0);
            const float p01 = ex2(sacc[nt][1] - nm0);
            const float p10 = ex2(sacc[nt][2] - nm1);
            const float p11 = ex2(sacc[nt][3] - nm1);
            ps0 += p00 + p01;
            ps1 += p10 + p11;
            __half2 hp0 = __floats2half2_rn(p00, p01);
            __half2 hp1 = __floats2half2_rn(p10, p11);
            *(uint32_t*)(sPw + gr * RB + (nt * 8 + gc * 2) * 2)       = *(uint32_t*)&hp0;
            *(uint32_t*)(sPw + (gr + 8) * RB + (nt * 8 + gc * 2) * 2) = *(uint32_t*)&hp1;
        }
        ps0 += __shfl_xor_sync(0xffffffffu, ps0, 1);
        ps0 += __shfl_xor_sync(0xffffffffu, ps0, 2);
        ps1 += __shfl_xor_sync(0xffffffffu, ps1, 1);
        ps1 += __shfl_xor_sync(0xffffffffu, ps1, 2);
        l0 = l0 * c0 + ps0;
        l1 = l1 * c1 + ps1;
        m0 = nm0; m1 = nm1;
        #pragma unroll
        for (int nt = 0; nt < 8; nt++) {
            oacc[nt][0] *= c0; oacc[nt][1] *= c0;
            oacc[nt][2] *= c1; oacc[nt][3] *= c1;
        }
        __syncwarp();

        // ---- O += P @ V : 4 ksteps x 8 nt
        #pragma unroll
        for (int ks = 0; ks < 4; ks++) {
            uint32_t af[4];
            ldm_x4(af, aP + ks * 32);
            #pragma unroll
            for (int nt = 0; nt < 8; nt++) {
                uint32_t b0, b1;
                ldm_x2t(b0, b1, bV + ks * 16 * RB + nt * 16);
                mma_f16(oacc[nt], af[0], af[1], af[2], af[3], b0, b1);
            }
        }
        __syncthreads();   // protect sK/sV before next commit
    }

    // epilogue -> fp16
    const float inv0 = 1.0f / l0;
    const float inv1 = 1.0f / l1;
    __half* O0 = O + base + (size_t)(q0 + wq0 + gr) * EMB;
    __half* O1 = O + base + (size_t)(q0 + wq0 + gr + 8) * EMB;
    #pragma unroll
    for (int nt = 0; nt < 8; nt++) {
        const int cn = nt * 8 + gc * 2;
        __half2 h0 = __floats2half2_rn(oacc[nt][0] * inv0, oacc[nt][1] * inv0);
        __half2 h1 = __floats2half2_rn(oacc[nt][2] * inv1, oacc[nt][3] * inv1);
        *(uint32_t*)(O0 + cn) = *(uint32_t*)&h0;
        *(uint32_t*)(O1 + cn) = *(uint32_t*)&h1;
    }
}

// ---------------------------------------------------------------------------
// Launch
// ---------------------------------------------------------------------------
extern "C" void kernel_launch(void* const* d_in, const int* in_sizes, int n_in,
                              void* d_out, int out_size)
{
    const float* x    = (const float*)d_in[0];
    const float* ln1g = (const float*)d_in[1];
    const float* ln1b = (const float*)d_in[2];
    const float* ln2g = (const float*)d_in[3];
    const float* ln2b = (const float*)d_in[4];
    const float* Wq   = (const float*)d_in[5];
    const float* bq   = (const float*)d_in[6];
    const float* Wk   = (const float*)d_in[7];
    const float* bk   = (const float*)d_in[8];
    const float* Wv   = (const float*)d_in[9];
    const float* bv   = (const float*)d_in[10];
    const float* Wo   = (const float*)d_in[11];
    const float* bo   = (const float*)d_in[12];
    const float* W1   = (const float*)d_in[13];
    const float* b1   = (const float*)d_in[14];
    const float* W2   = (const float*)d_in[15];
    const float* b2   = (const float*)d_in[16];
    float* out = (float*)d_out;

    __half *xn, *att, *xn2, *hb;
    float *q, *k, *v, *x2;
    __half *wq16, *wk16, *wv16, *wo16, *w116, *w216;
    cudaGetSymbolAddress((void**)&xn,  g_xn);
    cudaGetSymbolAddress((void**)&q,   g_q);
    cudaGetSymbolAddress((void**)&k,   g_k);
    cudaGetSymbolAddress((void**)&v,   g_v);
    cudaGetSymbolAddress((void**)&att, g_att);
    cudaGetSymbolAddress((void**)&x2,  g_x2);
    cudaGetSymbolAddress((void**)&xn2, g_xn2);
    cudaGetSymbolAddress((void**)&hb,  g_h);
    cudaGetSymbolAddress((void**)&wq16, g_wq16);
    cudaGetSymbolAddress((void**)&wk16, g_wk16);
    cudaGetSymbolAddress((void**)&wv16, g_wv16);
    cudaGetSymbolAddress((void**)&wo16, g_wo16);
    cudaGetSymbolAddress((void**)&w116, g_w116);
    cudaGetSymbolAddress((void**)&w216, g_w216);

    cudaFuncSetAttribute(attn4_kernel,
                         cudaFuncAttributeMaxDynamicSharedMemorySize, ATT_SMEM);
    cudaFuncSetAttribute(hgemm_kernel<1>,
                         cudaFuncAttributeMaxDynamicSharedMemorySize, CP_SMEM);
    cudaFuncSetAttribute(hgemm_kernel<2>,
                         cudaFuncAttributeMaxDynamicSharedMemorySize, CP_SMEM);
    cudaFuncSetAttribute(qkvh_kernel,
                         cudaFuncAttributeMaxDynamicSharedMemorySize, CP_SMEM);

    const dim3 blk(256);
    const dim3 gEmb(EMB / BN, MTOT / BM);        // (4, 32)
    const dim3 gMlp(MLPH / BN, MTOT / BM);       // (16, 32)
    const dim3 gQKV(EMB / BN, MTOT / BM, 3);
    const dim3 gAtt(SEQ / AQT, BATCH * HEADS);

    // 0. Weight convert fp32 -> fp16
    const int c1m = EMB * EMB / 4, c4m = EMB * MLPH / 4;
    wconv_kernel<<<(c1m + 255) / 256, blk>>>(Wq, wq16, c1m);
    wconv_kernel<<<(c1m + 255) / 256, blk>>>(Wk, wk16, c1m);
    wconv_kernel<<<(c1m + 255) / 256, blk>>>(Wv, wv16, c1m);
    wconv_kernel<<<(c1m + 255) / 256, blk>>>(Wo, wo16, c1m);
    wconv_kernel<<<(c4m + 255) / 256, blk>>>(W1, w116, c4m);
    wconv_kernel<<<(c4m + 255) / 256, blk>>>(W2, w216, c4m);

    // 1. LN1 (-> fp16)
    ln_kernel<<<MTOT, blk>>>(x, ln1g, ln1b, xn);
    // 2. QKV projections (fp16 tensor cores)
    qkvh_kernel<<<gQKV, blk, CP_SMEM>>>(xn, wq16, wk16, wv16, bq, bk, bv, q, k, v);
    // 3. Attention (fp16 tensor cores, -> fp16)
    attn4_kernel<<<gAtt, blk, ATT_SMEM>>>(q, k, v, att);
    // 4. Output projection + residual
    hgemm_kernel<2><<<gEmb, blk, CP_SMEM>>>(att, wo16, bo, x, x2, MTOT, EMB, EMB);
    // 5. LN2 (-> fp16)
    ln_kernel<<<MTOT, blk>>>(x2, ln2g, ln2b, xn2);
    // 6. MLP up + ReLU (-> fp16)
    hgemm_kernel<1><<<gMlp, blk, CP_SMEM>>>(xn2, w116, b1, nullptr, (float*)hb,
                                            MTOT, MLPH, EMB);
    // 7. MLP down + residual -> output
    hgemm_kernel<2><<<gEmb, blk, CP_SMEM>>>(hb, w216, b2, x2, out, MTOT, EMB, MLPH);
}